// round 8
// baseline (speedup 1.0000x reference)
#include <cuda_runtime.h>
#include <cuda_bf16.h>
#include <stdint.h>
#include <math.h>

// Problem constants
#define Bsz 2
#define Cch 512
#define Gg  8
#define Cg  64
#define Pp  1024          // H*W
#define P2  64            // H2*W2
#define SCALE 0.125f

// ---------------- scratch ----------------
__device__ float g_xn  [Bsz*Cch*Pp];
__device__ float g_q   [Bsz*Cch*Pp];
__device__ float g_off1[16*Cg*P2];
__device__ float g_grid[16*P2*2];
__device__ float g_k   [Bsz*Cch*P2];
__device__ float g_v   [Bsz*Cch*P2];
__device__ float g_bias[16*P2*Pp];       // TRANSPOSED: [bg][j][i]
__device__ float g_ao  [Bsz*Cch*Pp];
__device__ float g_x1  [Bsz*Cch*Pp];
__device__ float g_m1  [Bsz*2048*Pp];
__device__ float g_bnsc[Cch];
__device__ float g_bnsh[Cch];
__device__ __nv_bfloat16 g_w1t[128*128];

// ---------------- cp.async helpers ----------------
__device__ __forceinline__ void cp16(uint32_t dst, const void* src) {
    asm volatile("cp.async.ca.shared.global [%0], [%1], 16;" :: "r"(dst), "l"(src));
}
__device__ __forceinline__ void cp_commit() { asm volatile("cp.async.commit_group;"); }
template<int N> __device__ __forceinline__ void cp_wait() {
    asm volatile("cp.async.wait_group %0;" :: "n"(N));
}

// ---------------- batchnorm (full) ----------------
__global__ void bn_kernel(const float* __restrict__ x, const float* __restrict__ g,
                          const float* __restrict__ b, float* __restrict__ y) {
    int c = blockIdx.x, t = threadIdx.x;
    __shared__ float ssum[256], ssq[256];
    float s = 0.f, q = 0.f;
    for (int idx = t; idx < 2048; idx += 256) {
        int bb = idx >> 10, p = idx & 1023;
        float v = x[bb*(Cch*Pp) + c*Pp + p];
        s += v; q += v*v;
    }
    ssum[t] = s; ssq[t] = q; __syncthreads();
    for (int o = 128; o > 0; o >>= 1) {
        if (t < o) { ssum[t] += ssum[t+o]; ssq[t] += ssq[t+o]; }
        __syncthreads();
    }
    float m  = ssum[0] * (1.f/2048.f);
    float var = ssq[0] * (1.f/2048.f) - m*m;
    float rs = rsqrtf(var + 1e-5f);
    float gg = g[c] * rs;
    float bb2 = b[c] - m * gg;
    for (int idx = t; idx < 2048; idx += 256) {
        int bb = idx >> 10, p = idx & 1023;
        y[bb*(Cch*Pp) + c*Pp + p] = x[bb*(Cch*Pp) + c*Pp + p] * gg + bb2;
    }
}

// ---------------- batchnorm stats only ----------------
__global__ void bn_stats_kernel(const float* __restrict__ x, const float* __restrict__ g,
                                const float* __restrict__ b, float* __restrict__ sc,
                                float* __restrict__ sh) {
    int c = blockIdx.x, t = threadIdx.x;
    __shared__ float ssum[256], ssq[256];
    float s = 0.f, q = 0.f;
    for (int idx = t; idx < 2048; idx += 256) {
        int bb = idx >> 10, p = idx & 1023;
        float v = x[bb*(Cch*Pp) + c*Pp + p];
        s += v; q += v*v;
    }
    ssum[t] = s; ssq[t] = q; __syncthreads();
    for (int o = 128; o > 0; o >>= 1) {
        if (t < o) { ssum[t] += ssum[t+o]; ssq[t] += ssq[t+o]; }
        __syncthreads();
    }
    if (t == 0) {
        float m  = ssum[0] * (1.f/2048.f);
        float var = ssq[0] * (1.f/2048.f) - m*m;
        float rs = rsqrtf(var + 1e-5f);
        float gg = g[c] * rs;
        sc[c] = gg;
        sh[c] = b[c] - m * gg;
    }
}

// ---------------- grouped 1x1 conv (q) ----------------
__global__ void gconv_kernel(const float* __restrict__ in, const float* __restrict__ w,
                             float* __restrict__ out, int P) {
    int bg = blockIdx.x, pt = blockIdx.y;
    int grp = bg & 7;
    const float* A  = in + (size_t)bg*Cg*P + pt*64;
    const float* Wg = w + grp*4096;
    float* O        = out + (size_t)bg*Cg*P + pt*64;
    __shared__ float As[64][64];
    __shared__ float Ws[64][64];
    int t = threadIdx.x;
    for (int idx = t; idx < 4096; idx += 256) {
        int r = idx >> 6, q = idx & 63;
        As[r][q] = A[r*P + q];
        ((float*)Ws)[idx] = Wg[idx];
    }
    __syncthreads();
    int tp = (t & 15) * 4, to = (t >> 4) * 4;
    float acc[4][4] = {};
    #pragma unroll
    for (int c = 0; c < 64; c += 4) {
        float4 a[4], wv[4];
        #pragma unroll
        for (int u = 0; u < 4; u++) a[u] = *(const float4*)&As[c+u][tp];
        #pragma unroll
        for (int oi = 0; oi < 4; oi++) wv[oi] = *(const float4*)&Ws[to+oi][c];
        #pragma unroll
        for (int oi = 0; oi < 4; oi++) {
            float wf[4] = {wv[oi].x, wv[oi].y, wv[oi].z, wv[oi].w};
            #pragma unroll
            for (int u = 0; u < 4; u++) {
                acc[oi][0] += wf[u]*a[u].x; acc[oi][1] += wf[u]*a[u].y;
                acc[oi][2] += wf[u]*a[u].z; acc[oi][3] += wf[u]*a[u].w;
            }
        }
    }
    #pragma unroll
    for (int oi = 0; oi < 4; oi++)
        #pragma unroll
        for (int pj = 0; pj < 4; pj++)
            O[(to+oi)*P + tp+pj] = acc[oi][pj];
}

// ---------------- depthwise conv + gelu ----------------
__global__ void dwconv_kernel(const float* __restrict__ q, const float* __restrict__ dw,
                              const float* __restrict__ db, float* __restrict__ out) {
    int idx = blockIdx.x*blockDim.x + threadIdx.x;
    if (idx >= 16*Cg*P2) return;
    int p = idx & 63, c = (idx >> 6) & 63, bg = idx >> 12;
    int oy = p >> 3, ox = p & 7;
    float acc = db[c];
    const float* ip = q + (size_t)bg*Cg*Pp + c*Pp;
    const float* wp = dw + c*36;
    #pragma unroll
    for (int ky = 0; ky < 6; ky++) {
        int iy = oy*4 - 1 + ky;
        if (iy < 0 || iy >= 32) continue;
        #pragma unroll
        for (int kx = 0; kx < 6; kx++) {
            int ix = ox*4 - 1 + kx;
            if (ix < 0 || ix >= 32) continue;
            acc += ip[iy*32 + ix] * wp[ky*6 + kx];
        }
    }
    out[idx] = 0.5f * acc * (1.f + erff(acc * 0.70710678118654752f));
}

// ---------------- pointwise offsets -> grid ----------------
__global__ void offset_kernel(const float* __restrict__ off1, const float* __restrict__ pw,
                              float* __restrict__ grid) {
    __shared__ float part[2][4][64];
    int bg = blockIdx.x, t = threadIdx.x;
    int qd = t >> 6, p = t & 63;
    const float* base = off1 + bg*(Cg*P2);
    float s0 = 0.f, s1 = 0.f;
    #pragma unroll
    for (int cc = 0; cc < 16; cc++) {
        int c = qd*16 + cc;
        float v = base[c*64 + p];
        s0 = fmaf(v, pw[c], s0);
        s1 = fmaf(v, pw[64 + c], s1);
    }
    part[0][qd][p] = s0;
    part[1][qd][p] = s1;
    __syncthreads();
    if (t < 64) {
        float t0 = part[0][0][t] + part[0][1][t] + part[0][2][t] + part[0][3][t];
        float t1 = part[1][0][t] + part[1][1][t] + part[1][2][t] + part[1][3][t];
        float ox = tanhf(t0) * 4.f, oy = tanhf(t1) * 4.f;
        float gx = (float)(t & 7), gy = (float)(t >> 3);
        grid[bg*128 + t*2]   = 2.f * (gx + ox) * (1.f/7.f) - 1.f;
        grid[bg*128 + t*2+1] = 2.f * (gy + oy) * (1.f/7.f) - 1.f;
    }
}

// ---------------- gconv k,v with inline bilinear sampling ----------------
__global__ void gconv_kv_kernel(const float* __restrict__ xn, const float* __restrict__ grid,
                                const float* __restrict__ kw, const float* __restrict__ vw,
                                float* __restrict__ kout, float* __restrict__ vout) {
    const int P = P2;
    int bg = blockIdx.x;
    int grp = bg & 7;
    __shared__ float sgrid[128];
    __shared__ float As[64][64];
    __shared__ float Wk[64][64];
    __shared__ float Wv[64][64];
    int t = threadIdx.x;
    if (t < 128) sgrid[t] = grid[bg*128 + t];
    for (int idx = t; idx < 4096; idx += 256) {
        ((float*)Wk)[idx] = kw[grp*4096 + idx];
        ((float*)Wv)[idx] = vw[grp*4096 + idx];
    }
    __syncthreads();
    for (int idx = t; idx < 4096; idx += 256) {
        int p = idx & 63, c = idx >> 6;
        float vx = sgrid[p*2], vy = sgrid[p*2+1];
        float x = ((vx + 1.f) * 32.f - 1.f) * 0.5f;
        float y = ((vy + 1.f) * 32.f - 1.f) * 0.5f;
        float x0f = floorf(x), y0f = floorf(y);
        int x0 = (int)x0f, y0 = (int)y0f;
        float wx = x - x0f, wy = y - y0f;
        const float* im = xn + (size_t)bg*Cg*Pp + c*Pp;
        float v00 = (x0   >= 0 && x0   < 32 && y0   >= 0 && y0   < 32) ? im[y0*32 + x0]       : 0.f;
        float v10 = (x0+1 >= 0 && x0+1 < 32 && y0   >= 0 && y0   < 32) ? im[y0*32 + x0+1]     : 0.f;
        float v01 = (x0   >= 0 && x0   < 32 && y0+1 >= 0 && y0+1 < 32) ? im[(y0+1)*32 + x0]   : 0.f;
        float v11 = (x0+1 >= 0 && x0+1 < 32 && y0+1 >= 0 && y0+1 < 32) ? im[(y0+1)*32 + x0+1] : 0.f;
        As[c][p] = v00*(1.f-wx)*(1.f-wy) + v10*wx*(1.f-wy) + v01*(1.f-wx)*wy + v11*wx*wy;
    }
    __syncthreads();
    int tp = (t & 15) * 4, to = (t >> 4) * 4;
    float ak[4][4] = {}, av[4][4] = {};
    #pragma unroll
    for (int c = 0; c < 64; c += 4) {
        float4 a[4], wk[4], wv[4];
        #pragma unroll
        for (int u = 0; u < 4; u++) a[u] = *(const float4*)&As[c+u][tp];
        #pragma unroll
        for (int oi = 0; oi < 4; oi++) {
            wk[oi] = *(const float4*)&Wk[to+oi][c];
            wv[oi] = *(const float4*)&Wv[to+oi][c];
        }
        #pragma unroll
        for (int oi = 0; oi < 4; oi++) {
            float kf[4] = {wk[oi].x, wk[oi].y, wk[oi].z, wk[oi].w};
            float vf[4] = {wv[oi].x, wv[oi].y, wv[oi].z, wv[oi].w};
            #pragma unroll
            for (int u = 0; u < 4; u++) {
                ak[oi][0] += kf[u]*a[u].x; ak[oi][1] += kf[u]*a[u].y;
                ak[oi][2] += kf[u]*a[u].z; ak[oi][3] += kf[u]*a[u].w;
                av[oi][0] += vf[u]*a[u].x; av[oi][1] += vf[u]*a[u].y;
                av[oi][2] += vf[u]*a[u].z; av[oi][3] += vf[u]*a[u].w;
            }
        }
    }
    float* KO = kout + (size_t)bg*Cg*P;
    float* VO = vout + (size_t)bg*Cg*P;
    #pragma unroll
    for (int oi = 0; oi < 4; oi++)
        #pragma unroll
        for (int pj = 0; pj < 4; pj++) {
            KO[(to+oi)*P + tp+pj] = ak[oi][pj];
            VO[(to+oi)*P + tp+pj] = av[oi][pj];
        }
}

// ---------------- one-time W1 -> bf16 ----------------
__global__ void w1cvt_kernel(const float* __restrict__ w1) {
    int idx = blockIdx.x*256 + threadIdx.x;  // 16384
    int s = idx >> 7, n = idx & 127;
    g_w1t[n*128 + s] = __float2bfloat16(w1[idx]);
}

// ======================= CPB bias MLP — bf16 tensor cores =======================
#define BPAD 136

__device__ __forceinline__ void ldsm4(uint32_t addr, uint32_t& r0, uint32_t& r1,
                                      uint32_t& r2, uint32_t& r3) {
    asm volatile("ldmatrix.sync.aligned.m8n8.x4.shared.b16 {%0,%1,%2,%3}, [%4];"
                 : "=r"(r0), "=r"(r1), "=r"(r2), "=r"(r3) : "r"(addr));
}
__device__ __forceinline__ void mma_bf16(float* c, const uint32_t* a, uint32_t b0, uint32_t b1) {
    asm volatile("mma.sync.aligned.m16n8k16.row.col.f32.bf16.bf16.f32 "
                 "{%0,%1,%2,%3}, {%4,%5,%6,%7}, {%8,%9}, {%0,%1,%2,%3};"
                 : "+f"(c[0]), "+f"(c[1]), "+f"(c[2]), "+f"(c[3])
                 : "r"(a[0]), "r"(a[1]), "r"(a[2]), "r"(a[3]), "r"(b0), "r"(b1));
}

__global__ __launch_bounds__(128, 3)
void bias_mma_kernel(const float* __restrict__ grid,
                     const float* __restrict__ w0, const float* __restrict__ b0,
                     const __nv_bfloat16* __restrict__ w1t,
                     const float* __restrict__ b1,
                     const float* __restrict__ w2, const float* __restrict__ b2,
                     float* __restrict__ bias) {
    extern __shared__ unsigned char smraw[];
    __nv_bfloat16* W1Ts = (__nv_bfloat16*)smraw;           // [n][s] 128 x BPAD
    __nv_bfloat16* H1s  = W1Ts + 128*BPAD;                 // [i][s] 128 x BPAD
    float* w0s = (float*)(H1s + 128*BPAD);
    float* b0s = w0s + 256;
    float* b1s = b0s + 128;
    float* w2s = b1s + 128;

    int t = threadIdx.x;
    int lane = t & 31, warp = t >> 5;
    int j = blockIdx.x, bg = blockIdx.y;

    {
        const uint4* src = (const uint4*)w1t;
        for (int idx = t; idx < 2048; idx += 128) {
            int n = idx >> 4, c16 = idx & 15;
            *(uint4*)(W1Ts + n*BPAD + c16*8) = src[idx];
        }
    }
    for (int idx = t; idx < 256; idx += 128) w0s[idx] = w0[idx];
    b0s[t] = b0[t];
    b1s[t] = b1[t];
    w2s[t] = w2[t];
    float kvx = grid[bg*128 + j*2], kvy = grid[bg*128 + j*2 + 1];
    float b2v = b2[0];
    __syncthreads();

    uint32_t h1base = (uint32_t)__cvta_generic_to_shared(H1s);
    uint32_t w1base = (uint32_t)__cvta_generic_to_shared(W1Ts);
    float* brow = bias + (size_t)bg*(P2*Pp) + (size_t)j*Pp;   // transposed: [bg][j][i]
    int m0 = 32*warp;

    for (int it = 0; it < 8; it++) {
        int i0 = it*128;
        {
            int i = i0 + t;
            float qx = 2.f * (float)(i & 31) * (1.f/31.f) - 1.f;
            float qy = 2.f * (float)(i >> 5) * (1.f/31.f) - 1.f;
            float px = qx - kvx, py = qy - kvy;
            float fx = copysignf(log1pf(fabsf(px)), px);
            float fy = copysignf(log1pf(fabsf(py)), py);
            __nv_bfloat162* rowp = (__nv_bfloat162*)(H1s + t*BPAD);
            #pragma unroll 8
            for (int s = 0; s < 128; s += 2) {
                float h0 = fmaxf(fmaf(fy, w0s[128+s],   fmaf(fx, w0s[s],   b0s[s])),   0.f);
                float h1v= fmaxf(fmaf(fy, w0s[128+s+1], fmaf(fx, w0s[s+1], b0s[s+1])), 0.f);
                rowp[s>>1] = __floats2bfloat162_rn(h0, h1v);
            }
        }
        __syncthreads();

        float rs[4] = {0.f, 0.f, 0.f, 0.f};
        int arow = (lane & 7) + ((lane >> 3) & 1) * 8;
        int acolq = (lane >> 4) * 8;
        int bn_off = (lane >> 4) * 8 + (lane & 7);
        int bcol = ((lane >> 3) & 1) * 8;

        for (int nh = 0; nh < 2; nh++) {
            float c[2][8][4] = {};
            #pragma unroll
            for (int k8 = 0; k8 < 8; k8++) {
                int k0 = k8 * 16;
                uint32_t A[2][4];
                #pragma unroll
                for (int mt = 0; mt < 2; mt++) {
                    int row = m0 + mt*16 + arow;
                    uint32_t addr = h1base + (uint32_t)(row*BPAD + k0 + acolq) * 2u;
                    ldsm4(addr, A[mt][0], A[mt][1], A[mt][2], A[mt][3]);
                }
                uint32_t Bf[4][4];
                #pragma unroll
                for (int np = 0; np < 4; np++) {
                    int n = nh*64 + np*16 + bn_off;
                    uint32_t addr = w1base + (uint32_t)(n*BPAD + k0 + bcol) * 2u;
                    ldsm4(addr, Bf[np][0], Bf[np][1], Bf[np][2], Bf[np][3]);
                }
                #pragma unroll
                for (int nt = 0; nt < 8; nt++) {
                    uint32_t bb0 = Bf[nt>>1][(nt&1)*2], bb1 = Bf[nt>>1][(nt&1)*2+1];
                    mma_bf16(c[0][nt], A[0], bb0, bb1);
                    mma_bf16(c[1][nt], A[1], bb0, bb1);
                }
            }
            #pragma unroll
            for (int nt = 0; nt < 8; nt++) {
                int n = nh*64 + nt*8 + 2*(lane & 3);
                float b1a = b1s[n], b1b = b1s[n+1];
                float w2a = w2s[n], w2b = w2s[n+1];
                #pragma unroll
                for (int mt = 0; mt < 2; mt++) {
                    rs[mt*2+0] += fmaxf(c[mt][nt][0]+b1a, 0.f)*w2a + fmaxf(c[mt][nt][1]+b1b, 0.f)*w2b;
                    rs[mt*2+1] += fmaxf(c[mt][nt][2]+b1a, 0.f)*w2a + fmaxf(c[mt][nt][3]+b1b, 0.f)*w2b;
                }
            }
        }
        #pragma unroll
        for (int k = 0; k < 4; k++) {
            rs[k] += __shfl_xor_sync(0xffffffffu, rs[k], 1);
            rs[k] += __shfl_xor_sync(0xffffffffu, rs[k], 2);
        }
        if ((lane & 3) == 0) {
            int gid = lane >> 2;
            #pragma unroll
            for (int mt = 0; mt < 2; mt++) {
                int i1 = i0 + m0 + mt*16 + gid;
                brow[i1]     = rs[mt*2+0] + b2v;
                brow[i1+8]   = rs[mt*2+1] + b2v;
            }
        }
        __syncthreads();
    }
}

// ======================= fused attention (transposed bias read) =======================
__global__ __launch_bounds__(128, 1)
void attn_fused_kernel(const float* __restrict__ q, const float* __restrict__ k,
                       const float* __restrict__ v, const float* __restrict__ bias,
                       float* __restrict__ out) {
    extern __shared__ float sm[];
    float* att = sm;               // [128][65]
    float* ks  = att + 128*65;     // [64][64]
    float* vs  = ks + 64*64;       // [64][64]

    int t = threadIdx.x;
    int i0 = blockIdx.x * 128, bh = blockIdx.y;
    int b = bh >> 3, h = bh & 7;

    const float* kb = k + ((size_t)b*Cch + h*64)*P2;
    const float* vb = v + ((size_t)b*Cch + h*64)*P2;
    const float* qb = q + ((size_t)b*Cch + h*64)*Pp;
    const float* bb = bias + (size_t)bh*(P2*Pp);    // [j][i]
    float* ob = out + ((size_t)b*Cch + h*64)*Pp;

    for (int idx = t; idx < 4096; idx += 128) {
        ks[idx] = kb[idx];
        vs[idx] = vb[idx];
    }
    for (int idx = t; idx < 128*64; idx += 128) {
        int jj = idx >> 7, i = idx & 127;    // coalesced over i
        att[i*65 + jj] = bb[(size_t)jj*Pp + i0 + i];
    }
    float ql[64];
    #pragma unroll
    for (int d = 0; d < 64; d++) ql[d] = qb[d*Pp + i0 + t] * SCALE;
    __syncthreads();

    float* arow = att + t*65;
    float mx = -1e30f;
    #pragma unroll 2
    for (int jj = 0; jj < 64; jj++) {
        float s = arow[jj];
        #pragma unroll
        for (int d = 0; d < 64; d++) s += ql[d] * ks[d*64 + jj];
        arow[jj] = s;
        mx = fmaxf(mx, s);
    }
    float sum = 0.f;
    #pragma unroll 4
    for (int jj = 0; jj < 64; jj++) {
        float e = __expf(arow[jj] - mx);
        arow[jj] = e;
        sum += e;
    }
    float inv = 1.f / sum;

    int i = i0 + t;
    #pragma unroll
    for (int half = 0; half < 2; half++) {
        float o[32];
        #pragma unroll
        for (int d = 0; d < 32; d++) o[d] = 0.f;
        #pragma unroll 2
        for (int jj = 0; jj < 64; jj++) {
            float a = arow[jj];
            #pragma unroll
            for (int d = 0; d < 32; d++) o[d] += a * vs[(half*32 + d)*64 + jj];
        }
        #pragma unroll
        for (int d = 0; d < 32; d++) ob[(size_t)(half*32 + d)*Pp + i] = o[d] * inv;
    }
}

// ======================= tf32 GEMM — cp.async double-buffered =======================
__device__ __forceinline__ uint32_t f2tf32(float v) {
    uint32_t u;
    asm("cvt.rna.tf32.f32 %0, %1;" : "=r"(u) : "f"(v));
    return u;
}
__device__ __forceinline__ void mma_tf32(float* c, const uint32_t* a, uint32_t b0, uint32_t b1) {
    asm volatile("mma.sync.aligned.m16n8k8.row.col.f32.tf32.tf32.f32 "
                 "{%0,%1,%2,%3}, {%4,%5,%6,%7}, {%8,%9}, {%0,%1,%2,%3};"
                 : "+f"(c[0]), "+f"(c[1]), "+f"(c[2]), "+f"(c[3])
                 : "r"(a[0]), "r"(a[1]), "r"(a[2]), "r"(a[3]), "r"(b0), "r"(b1));
}

#define WT_STRIDE 36
#define XT_STRIDE 136

__global__ __launch_bounds__(256)
void gemm_tf32_kernel(const float* __restrict__ A, const float* __restrict__ W,
                      const float* __restrict__ bias, const float* __restrict__ res,
                      float* __restrict__ out, int Cin, int act,
                      const float* __restrict__ bnsc, const float* __restrict__ bnsh) {
    const int P = 1024;
    int b = blockIdx.z;
    int O = gridDim.y * 128;
    int p0 = blockIdx.x * 128, o0 = blockIdx.y * 128;
    const float* Ab = A + (size_t)b*Cin*P;

    extern __shared__ float smf[];
    float* Wt = smf;                             // [2][128][36]
    float* Xt = Wt + 2*128*WT_STRIDE;            // [2][32][136]
    float* scs = Xt + 2*32*XT_STRIDE;            // [512]
    float* shs = scs + 512;                      // [512]

    int t = threadIdx.x;
    int lane = t & 31, warp = t >> 5;
    int gid = lane >> 2, ctid = lane & 3;
    int m0w = (warp >> 1) * 32, n0w = (warp & 1) * 64;

    bool useBN = (bnsc != nullptr);
    if (useBN) {
        for (int idx = t; idx < Cin; idx += 256) { scs[idx] = bnsc[idx]; shs[idx] = bnsh[idx]; }
    }

    uint32_t wtbase = (uint32_t)__cvta_generic_to_shared(Wt);
    uint32_t xtbase = (uint32_t)__cvta_generic_to_shared(Xt);

    int nch = Cin >> 5;
    float c[2][8][4] = {};

    // issue chunk 0
    {
        int cc = 0, st = 0;
        #pragma unroll 2
        for (int idx = t; idx < 1024; idx += 256) {
            int r = idx >> 3, q4 = (idx & 7) * 4;
            cp16(wtbase + (uint32_t)((st*128 + r)*WT_STRIDE + q4)*4u,
                 &W[(size_t)(o0 + r)*Cin + cc + q4]);
        }
        #pragma unroll 2
        for (int idx = t; idx < 1024; idx += 256) {
            int r = idx >> 5, q4 = (idx & 31) * 4;
            cp16(xtbase + (uint32_t)((st*32 + r)*XT_STRIDE + q4)*4u,
                 &Ab[(size_t)(cc + r)*P + p0 + q4]);
        }
        cp_commit();
    }

    for (int ch = 0; ch < nch; ch++) {
        int cc = ch << 5;
        int st = ch & 1;
        if (ch + 1 < nch) {
            int cc2 = cc + 32, st2 = st ^ 1;
            #pragma unroll 2
            for (int idx = t; idx < 1024; idx += 256) {
                int r = idx >> 3, q4 = (idx & 7) * 4;
                cp16(wtbase + (uint32_t)((st2*128 + r)*WT_STRIDE + q4)*4u,
                     &W[(size_t)(o0 + r)*Cin + cc2 + q4]);
            }
            #pragma unroll 2
            for (int idx = t; idx < 1024; idx += 256) {
                int r = idx >> 5, q4 = (idx & 31) * 4;
                cp16(xtbase + (uint32_t)((st2*32 + r)*XT_STRIDE + q4)*4u,
                     &Ab[(size_t)(cc2 + r)*P + p0 + q4]);
            }
            cp_commit();
            cp_wait<1>();
        } else {
            cp_wait<0>();
        }
        __syncthreads();

        float* WtS = Wt + st*128*WT_STRIDE;
        float* XtS = Xt + st*32*XT_STRIDE;
        #pragma unroll
        for (int k0 = 0; k0 < 32; k0 += 8) {
            float s0 = 1.f, h0 = 0.f, s4 = 1.f, h4 = 0.f;
            if (useBN) {
                s0 = scs[cc + k0 + ctid];     h0 = shs[cc + k0 + ctid];
                s4 = scs[cc + k0 + ctid + 4]; h4 = shs[cc + k0 + ctid + 4];
            }
            uint32_t a[2][4];
            #pragma unroll
            for (int mt = 0; mt < 2; mt++) {
                int row = m0w + mt*16;
                a[mt][0] = f2tf32(WtS[(row + gid    )*WT_STRIDE + k0 + ctid]);
                a[mt][1] = f2tf32(WtS[(row + 8 + gid)*WT_STRIDE + k0 + ctid]);
                a[mt][2] = f2tf32(WtS[(row + gid    )*WT_STRIDE + k0 + ctid + 4]);
                a[mt][3] = f2tf32(WtS[(row + 8 + gid)*WT_STRIDE + k0 + ctid + 4]);
            }
            #pragma unroll
            for (int nt = 0; nt < 8; nt++) {
                int n = n0w + nt*8 + gid;
                float x0 = XtS[(k0 + ctid    )*XT_STRIDE + n];
                float x1 = XtS[(k0 + ctid + 4)*XT_STRIDE + n];
                uint32_t b0v = f2tf32(useBN ? fmaf(x0, s0, h0) : x0);
                uint32_t b1v = f2tf32(useBN ? fmaf(x1, s4, h4) : x1);
                mma_tf32(c[0][nt], a[0], b0v, b1v);
                mma_tf32(c[1][nt], a[1], b0v, b1v);
            }
        }
        __syncthreads();
    }

    float* ob = out + (size_t)b*O*P;
    const float* rb = res ? res + (size_t)b*O*P : nullptr;
    #pragma unroll
    for (int mt = 0; mt < 2; mt++) {
        #pragma unroll
        for (int half = 0; half < 2; half++) {
            int o = o0 + m0w + mt*16 + gid + half*8;
            float bv = bias[o];
            #pragma unroll
            for (int nt = 0; nt < 8; nt++) {
                int p = p0 + n0w + nt*8 + 2*ctid;
                float v0 = c[mt][nt][half*2+0] + bv;
                float v1 = c[mt][nt][half*2+1] + bv;
                if (act == 1) {
                    v0 = 0.5f * v0 * (1.f + erff(v0 * 0.70710678118654752f));
                    v1 = 0.5f * v1 * (1.f + erff(v1 * 0.70710678118654752f));
                }
                if (rb) {
                    const float2 rv = *(const float2*)&rb[(size_t)o*P + p];
                    v0 += rv.x; v1 += rv.y;
                }
                float2 st2; st2.x = v0; st2.y = v1;
                *(float2*)&ob[(size_t)o*P + p] = st2;
            }
        }
    }
}

// ---------------- launch ----------------
extern "C" void kernel_launch(void* const* d_in, const int* in_sizes, int n_in,
                              void* d_out, int out_size) {
    const float* x        = (const float*)d_in[0];
    const float* n1_g     = (const float*)d_in[1];
    const float* n1_b     = (const float*)d_in[2];
    const float* n2_g     = (const float*)d_in[3];
    const float* n2_b     = (const float*)d_in[4];
    const float* q_w      = (const float*)d_in[5];
    const float* k_w      = (const float*)d_in[6];
    const float* v_w      = (const float*)d_in[7];
    const float* off_dw_w = (const float*)d_in[8];
    const float* off_dw_b = (const float*)d_in[9];
    const float* off_pw_w = (const float*)d_in[10];
    const float* cpb_w0   = (const float*)d_in[11];
    const float* cpb_b0   = (const float*)d_in[12];
    const float* cpb_w1   = (const float*)d_in[13];
    const float* cpb_b1   = (const float*)d_in[14];
    const float* cpb_w2   = (const float*)d_in[15];
    const float* cpb_b2   = (const float*)d_in[16];
    const float* out_w    = (const float*)d_in[17];
    const float* out_b    = (const float*)d_in[18];
    const float* mlp_w1   = (const float*)d_in[19];
    const float* mlp_b1   = (const float*)d_in[20];
    const float* mlp_w2   = (const float*)d_in[21];
    const float* mlp_b2   = (const float*)d_in[22];
    float* out = (float*)d_out;

    float *p_xn, *p_q, *p_off1, *p_grid, *p_k, *p_v, *p_bias, *p_ao, *p_x1, *p_m1, *p_sc, *p_sh;
    __nv_bfloat16* p_w1t;
    cudaGetSymbolAddress((void**)&p_xn,   g_xn);
    cudaGetSymbolAddress((void**)&p_q,    g_q);
    cudaGetSymbolAddress((void**)&p_off1, g_off1);
    cudaGetSymbolAddress((void**)&p_grid, g_grid);
    cudaGetSymbolAddress((void**)&p_k,    g_k);
    cudaGetSymbolAddress((void**)&p_v,    g_v);
    cudaGetSymbolAddress((void**)&p_bias, g_bias);
    cudaGetSymbolAddress((void**)&p_ao,   g_ao);
    cudaGetSymbolAddress((void**)&p_x1,   g_x1);
    cudaGetSymbolAddress((void**)&p_m1,   g_m1);
    cudaGetSymbolAddress((void**)&p_sc,   g_bnsc);
    cudaGetSymbolAddress((void**)&p_sh,   g_bnsh);
    cudaGetSymbolAddress((void**)&p_w1t,  g_w1t);

    int gemm_smem = (2*128*WT_STRIDE + 2*32*XT_STRIDE + 1024) * 4;
    cudaFuncSetAttribute(gemm_tf32_kernel, cudaFuncAttributeMaxDynamicSharedMemorySize, gemm_smem);

    // launches 1-5 (so bias_mma is launch #6 for ncu -s 5 -c 1)
    bn_kernel<<<512, 256>>>(x, n1_g, n1_b, p_xn);                          // 1
    gconv_kernel<<<dim3(16, 16), 256>>>(p_xn, q_w, p_q, Pp);               // 2
    dwconv_kernel<<<256, 256>>>(p_q, off_dw_w, off_dw_b, p_off1);          // 3
    offset_kernel<<<16, 256>>>(p_off1, off_pw_w, p_grid);                  // 4
    w1cvt_kernel<<<64, 256>>>(cpb_w1);                                     // 5
    // 6: CPB bias MLP  <-- profiled
    {
        int smem = 2*128*BPAD*2 + (256 + 128 + 128 + 128)*4;
        cudaFuncSetAttribute(bias_mma_kernel, cudaFuncAttributeMaxDynamicSharedMemorySize, smem);
        bias_mma_kernel<<<dim3(64, 16), 128, smem>>>(p_grid, cpb_w0, cpb_b0, p_w1t, cpb_b1,
                                                     cpb_w2, cpb_b2, p_bias);
    }
    gconv_kv_kernel<<<16, 256>>>(p_xn, p_grid, k_w, v_w, p_k, p_v);        // 7
    {
        int smem = (128*65 + 64*64 + 64*64) * 4;
        cudaFuncSetAttribute(attn_fused_kernel, cudaFuncAttributeMaxDynamicSharedMemorySize, smem);
        attn_fused_kernel<<<dim3(8, 16), 128, smem>>>(p_q, p_k, p_v, p_bias, p_ao);  // 8
    }
    gemm_tf32_kernel<<<dim3(8, 4, 2), 256, gemm_smem>>>(p_ao, out_w, out_b, x, p_x1, 512, 0, nullptr, nullptr);   // 9
    bn_stats_kernel<<<512, 256>>>(p_x1, n2_g, n2_b, p_sc, p_sh);           // 10
    gemm_tf32_kernel<<<dim3(8, 16, 2), 256, gemm_smem>>>(p_x1, mlp_w1, mlp_b1, nullptr, p_m1, 512, 1, p_sc, p_sh); // 11
    gemm_tf32_kernel<<<dim3(8, 4, 2), 256, gemm_smem>>>(p_m1, mlp_w2, mlp_b2, p_x1, out, 2048, 0, nullptr, nullptr); // 12
}

// round 9
// speedup vs baseline: 1.4235x; 1.4235x over previous
#include <cuda_runtime.h>
#include <cuda_bf16.h>
#include <stdint.h>
#include <math.h>

// Problem constants
#define Bsz 2
#define Cch 512
#define Gg  8
#define Cg  64
#define Pp  1024          // H*W
#define P2  64            // H2*W2
#define SCALE 0.125f

// ---------------- scratch ----------------
__device__ float g_xn  [Bsz*Cch*Pp];
__device__ float g_q   [Bsz*Cch*Pp];
__device__ float g_grid[16*P2*2];
__device__ float g_k   [Bsz*Cch*P2];
__device__ float g_v   [Bsz*Cch*P2];
__device__ float g_bias[16*P2*Pp];       // [bg][j][i]
__device__ float g_ao  [Bsz*Cch*Pp];
__device__ float g_x1  [Bsz*Cch*Pp];
__device__ float g_m1  [Bsz*2048*Pp];
__device__ float g_bnsc[Cch];
__device__ float g_bnsh[Cch];

// ---------------- batchnorm (full) ----------------
__global__ void bn_kernel(const float* __restrict__ x, const float* __restrict__ g,
                          const float* __restrict__ b, float* __restrict__ y) {
    int c = blockIdx.x, t = threadIdx.x;
    __shared__ float ssum[256], ssq[256];
    float s = 0.f, q = 0.f;
    for (int idx = t; idx < 2048; idx += 256) {
        int bb = idx >> 10, p = idx & 1023;
        float v = x[bb*(Cch*Pp) + c*Pp + p];
        s += v; q += v*v;
    }
    ssum[t] = s; ssq[t] = q; __syncthreads();
    for (int o = 128; o > 0; o >>= 1) {
        if (t < o) { ssum[t] += ssum[t+o]; ssq[t] += ssq[t+o]; }
        __syncthreads();
    }
    float m  = ssum[0] * (1.f/2048.f);
    float var = ssq[0] * (1.f/2048.f) - m*m;
    float rs = rsqrtf(var + 1e-5f);
    float gg = g[c] * rs;
    float bb2 = b[c] - m * gg;
    for (int idx = t; idx < 2048; idx += 256) {
        int bb = idx >> 10, p = idx & 1023;
        y[bb*(Cch*Pp) + c*Pp + p] = x[bb*(Cch*Pp) + c*Pp + p] * gg + bb2;
    }
}

// ---------------- batchnorm stats only ----------------
__global__ void bn_stats_kernel(const float* __restrict__ x, const float* __restrict__ g,
                                const float* __restrict__ b, float* __restrict__ sc,
                                float* __restrict__ sh) {
    int c = blockIdx.x, t = threadIdx.x;
    __shared__ float ssum[256], ssq[256];
    float s = 0.f, q = 0.f;
    for (int idx = t; idx < 2048; idx += 256) {
        int bb = idx >> 10, p = idx & 1023;
        float v = x[bb*(Cch*Pp) + c*Pp + p];
        s += v; q += v*v;
    }
    ssum[t] = s; ssq[t] = q; __syncthreads();
    for (int o = 128; o > 0; o >>= 1) {
        if (t < o) { ssum[t] += ssum[t+o]; ssq[t] += ssq[t+o]; }
        __syncthreads();
    }
    if (t == 0) {
        float m  = ssum[0] * (1.f/2048.f);
        float var = ssq[0] * (1.f/2048.f) - m*m;
        float rs = rsqrtf(var + 1e-5f);
        float gg = g[c] * rs;
        sc[c] = gg;
        sh[c] = b[c] - m * gg;
    }
}

// ---------------- grouped 1x1 conv (q) ----------------
__global__ void gconv_kernel(const float* __restrict__ in, const float* __restrict__ w,
                             float* __restrict__ out, int P) {
    int bg = blockIdx.x, pt = blockIdx.y;
    int grp = bg & 7;
    const float* A  = in + (size_t)bg*Cg*P + pt*64;
    const float* Wg = w + grp*4096;
    float* O        = out + (size_t)bg*Cg*P + pt*64;
    __shared__ float As[64][64];
    __shared__ float Ws[64][64];
    int t = threadIdx.x;
    for (int idx = t; idx < 4096; idx += 256) {
        int r = idx >> 6, q = idx & 63;
        As[r][q] = A[r*P + q];
        ((float*)Ws)[idx] = Wg[idx];
    }
    __syncthreads();
    int tp = (t & 15) * 4, to = (t >> 4) * 4;
    float acc[4][4] = {};
    #pragma unroll
    for (int c = 0; c < 64; c += 4) {
        float4 a[4], wv[4];
        #pragma unroll
        for (int u = 0; u < 4; u++) a[u] = *(const float4*)&As[c+u][tp];
        #pragma unroll
        for (int oi = 0; oi < 4; oi++) wv[oi] = *(const float4*)&Ws[to+oi][c];
        #pragma unroll
        for (int oi = 0; oi < 4; oi++) {
            float wf[4] = {wv[oi].x, wv[oi].y, wv[oi].z, wv[oi].w};
            #pragma unroll
            for (int u = 0; u < 4; u++) {
                acc[oi][0] += wf[u]*a[u].x; acc[oi][1] += wf[u]*a[u].y;
                acc[oi][2] += wf[u]*a[u].z; acc[oi][3] += wf[u]*a[u].w;
            }
        }
    }
    #pragma unroll
    for (int oi = 0; oi < 4; oi++)
        #pragma unroll
        for (int pj = 0; pj < 4; pj++)
            O[(to+oi)*P + tp+pj] = acc[oi][pj];
}

// ---------------- fused depthwise conv+gelu -> pointwise offsets -> grid ----------------
// one block per bg, 512 threads
__global__ void dwoff_kernel(const float* __restrict__ q, const float* __restrict__ dw,
                             const float* __restrict__ db, const float* __restrict__ pw,
                             float* __restrict__ grid) {
    __shared__ float off1s[Cg*P2];
    __shared__ float part[2][8][64];
    int bg = blockIdx.x, t = threadIdx.x;

    for (int idx = t; idx < Cg*P2; idx += 512) {
        int p = idx & 63, c = idx >> 6;
        int oy = p >> 3, ox = p & 7;
        float acc = db[c];
        const float* ip = q + (size_t)bg*Cg*Pp + c*Pp;
        const float* wp = dw + c*36;
        #pragma unroll
        for (int ky = 0; ky < 6; ky++) {
            int iy = oy*4 - 1 + ky;
            if (iy < 0 || iy >= 32) continue;
            #pragma unroll
            for (int kx = 0; kx < 6; kx++) {
                int ix = ox*4 - 1 + kx;
                if (ix < 0 || ix >= 32) continue;
                acc += ip[iy*32 + ix] * wp[ky*6 + kx];
            }
        }
        off1s[idx] = 0.5f * acc * (1.f + erff(acc * 0.70710678118654752f));
    }
    __syncthreads();

    int qd = t >> 6, p = t & 63;
    float s0 = 0.f, s1 = 0.f;
    #pragma unroll
    for (int cc = 0; cc < 8; cc++) {
        int c = qd*8 + cc;
        float v = off1s[c*64 + p];
        s0 = fmaf(v, pw[c], s0);
        s1 = fmaf(v, pw[64 + c], s1);
    }
    part[0][qd][p] = s0;
    part[1][qd][p] = s1;
    __syncthreads();
    if (t < 64) {
        float t0 = 0.f, t1 = 0.f;
        #pragma unroll
        for (int u = 0; u < 8; u++) { t0 += part[0][u][t]; t1 += part[1][u][t]; }
        float ox = tanhf(t0) * 4.f, oy = tanhf(t1) * 4.f;
        float gx = (float)(t & 7), gy = (float)(t >> 3);
        grid[bg*128 + t*2]   = 2.f * (gx + ox) * (1.f/7.f) - 1.f;
        grid[bg*128 + t*2+1] = 2.f * (gy + oy) * (1.f/7.f) - 1.f;
    }
}

// ======================= CPB bias MLP — bf16 tensor cores, 2 j's per block =======================
#define BPAD 136

__device__ __forceinline__ void ldsm4(uint32_t addr, uint32_t& r0, uint32_t& r1,
                                      uint32_t& r2, uint32_t& r3) {
    asm volatile("ldmatrix.sync.aligned.m8n8.x4.shared.b16 {%0,%1,%2,%3}, [%4];"
                 : "=r"(r0), "=r"(r1), "=r"(r2), "=r"(r3) : "r"(addr));
}
__device__ __forceinline__ void mma_bf16(float* c, const uint32_t* a, uint32_t b0, uint32_t b1) {
    asm volatile("mma.sync.aligned.m16n8k16.row.col.f32.bf16.bf16.f32 "
                 "{%0,%1,%2,%3}, {%4,%5,%6,%7}, {%8,%9}, {%0,%1,%2,%3};"
                 : "+f"(c[0]), "+f"(c[1]), "+f"(c[2]), "+f"(c[3])
                 : "r"(a[0]), "r"(a[1]), "r"(a[2]), "r"(a[3]), "r"(b0), "r"(b1));
}

__global__ __launch_bounds__(256, 2)
void bias_mma_kernel(const float* __restrict__ grid,
                     const float* __restrict__ w0, const float* __restrict__ b0,
                     const float* __restrict__ w1, const float* __restrict__ b1,
                     const float* __restrict__ w2, const float* __restrict__ b2,
                     float* __restrict__ bias) {
    extern __shared__ unsigned char smraw[];
    __nv_bfloat16* W1Ts = (__nv_bfloat16*)smraw;           // [n][s] 128 x BPAD (shared by both halves)
    __nv_bfloat16* H1sA = W1Ts + 128*BPAD;                 // half 0
    __nv_bfloat16* H1sB = H1sA + 128*BPAD;                 // half 1
    float* w0s = (float*)(H1sB + 128*BPAD);                // 256
    float* b0s = w0s + 256;                                // 128
    float* b1s = b0s + 128;                                // 128
    float* w2s = b1s + 128;                                // 128

    int t = threadIdx.x;                 // 256
    int half = t >> 7, wt = t & 127;
    int lane = t & 31, warp = (t >> 5) & 3;
    int j = blockIdx.x * 2 + half, bg = blockIdx.y;

    // stage W1^T (cvt from float), cooperative across 256 threads
    for (int idx = t; idx < 16384; idx += 256) {
        int s = idx >> 7, n = idx & 127;
        W1Ts[n*BPAD + s] = __float2bfloat16(w1[idx]);
    }
    if (t < 256) w0s[t] = w0[t];
    if (t < 128) { b0s[t] = b0[t]; b1s[t] = b1[t]; w2s[t] = w2[t]; }
    float kvx = grid[bg*128 + j*2], kvy = grid[bg*128 + j*2 + 1];
    float b2v = b2[0];
    __syncthreads();

    __nv_bfloat16* H1 = half ? H1sB : H1sA;
    uint32_t h1base = (uint32_t)__cvta_generic_to_shared(H1);
    uint32_t w1base = (uint32_t)__cvta_generic_to_shared(W1Ts);
    float* brow = bias + (size_t)bg*(P2*Pp) + (size_t)j*Pp;
    int m0 = 32*warp;

    for (int it = 0; it < 8; it++) {
        int i0 = it*128;
        {
            int i = i0 + wt;
            float qx = 2.f * (float)(i & 31) * (1.f/31.f) - 1.f;
            float qy = 2.f * (float)(i >> 5) * (1.f/31.f) - 1.f;
            float px = qx - kvx, py = qy - kvy;
            float fx = copysignf(log1pf(fabsf(px)), px);
            float fy = copysignf(log1pf(fabsf(py)), py);
            __nv_bfloat162* rowp = (__nv_bfloat162*)(H1 + wt*BPAD);
            #pragma unroll 8
            for (int s = 0; s < 128; s += 2) {
                float h0 = fmaxf(fmaf(fy, w0s[128+s],   fmaf(fx, w0s[s],   b0s[s])),   0.f);
                float h1v= fmaxf(fmaf(fy, w0s[128+s+1], fmaf(fx, w0s[s+1], b0s[s+1])), 0.f);
                rowp[s>>1] = __floats2bfloat162_rn(h0, h1v);
            }
        }
        __syncthreads();

        float rs[4] = {0.f, 0.f, 0.f, 0.f};
        int arow = (lane & 7) + ((lane >> 3) & 1) * 8;
        int acolq = (lane >> 4) * 8;
        int bn_off = (lane >> 4) * 8 + (lane & 7);
        int bcol = ((lane >> 3) & 1) * 8;

        for (int nh = 0; nh < 2; nh++) {
            float c[2][8][4] = {};
            #pragma unroll
            for (int k8 = 0; k8 < 8; k8++) {
                int k0 = k8 * 16;
                uint32_t A[2][4];
                #pragma unroll
                for (int mt = 0; mt < 2; mt++) {
                    int row = m0 + mt*16 + arow;
                    uint32_t addr = h1base + (uint32_t)(row*BPAD + k0 + acolq) * 2u;
                    ldsm4(addr, A[mt][0], A[mt][1], A[mt][2], A[mt][3]);
                }
                uint32_t Bf[4][4];
                #pragma unroll
                for (int np = 0; np < 4; np++) {
                    int n = nh*64 + np*16 + bn_off;
                    uint32_t addr = w1base + (uint32_t)(n*BPAD + k0 + bcol) * 2u;
                    ldsm4(addr, Bf[np][0], Bf[np][1], Bf[np][2], Bf[np][3]);
                }
                #pragma unroll
                for (int nt = 0; nt < 8; nt++) {
                    uint32_t bb0 = Bf[nt>>1][(nt&1)*2], bb1 = Bf[nt>>1][(nt&1)*2+1];
                    mma_bf16(c[0][nt], A[0], bb0, bb1);
                    mma_bf16(c[1][nt], A[1], bb0, bb1);
                }
            }
            #pragma unroll
            for (int nt = 0; nt < 8; nt++) {
                int n = nh*64 + nt*8 + 2*(lane & 3);
                float b1a = b1s[n], b1b = b1s[n+1];
                float w2a = w2s[n], w2b = w2s[n+1];
                #pragma unroll
                for (int mt = 0; mt < 2; mt++) {
                    rs[mt*2+0] += fmaxf(c[mt][nt][0]+b1a, 0.f)*w2a + fmaxf(c[mt][nt][1]+b1b, 0.f)*w2b;
                    rs[mt*2+1] += fmaxf(c[mt][nt][2]+b1a, 0.f)*w2a + fmaxf(c[mt][nt][3]+b1b, 0.f)*w2b;
                }
            }
        }
        #pragma unroll
        for (int k = 0; k < 4; k++) {
            rs[k] += __shfl_xor_sync(0xffffffffu, rs[k], 1);
            rs[k] += __shfl_xor_sync(0xffffffffu, rs[k], 2);
        }
        if ((lane & 3) == 0) {
            int gid = lane >> 2;
            #pragma unroll
            for (int mt = 0; mt < 2; mt++) {
                int i1 = i0 + m0 + mt*16 + gid;
                brow[i1]   = rs[mt*2+0] + b2v;
                brow[i1+8] = rs[mt*2+1] + b2v;
            }
        }
        __syncthreads();
    }
}

// ---------------- gconv k,v with inline bilinear sampling ----------------
__global__ void gconv_kv_kernel(const float* __restrict__ xn, const float* __restrict__ grid,
                                const float* __restrict__ kw, const float* __restrict__ vw,
                                float* __restrict__ kout, float* __restrict__ vout) {
    const int P = P2;
    int bg = blockIdx.x;
    int grp = bg & 7;
    __shared__ float sgrid[128];
    __shared__ float As[64][64];
    __shared__ float Wk[64][64];
    __shared__ float Wv[64][64];
    int t = threadIdx.x;
    if (t < 128) sgrid[t] = grid[bg*128 + t];
    for (int idx = t; idx < 4096; idx += 256) {
        ((float*)Wk)[idx] = kw[grp*4096 + idx];
        ((float*)Wv)[idx] = vw[grp*4096 + idx];
    }
    __syncthreads();
    for (int idx = t; idx < 4096; idx += 256) {
        int p = idx & 63, c = idx >> 6;
        float vx = sgrid[p*2], vy = sgrid[p*2+1];
        float x = ((vx + 1.f) * 32.f - 1.f) * 0.5f;
        float y = ((vy + 1.f) * 32.f - 1.f) * 0.5f;
        float x0f = floorf(x), y0f = floorf(y);
        int x0 = (int)x0f, y0 = (int)y0f;
        float wx = x - x0f, wy = y - y0f;
        const float* im = xn + (size_t)bg*Cg*Pp + c*Pp;
        float v00 = (x0   >= 0 && x0   < 32 && y0   >= 0 && y0   < 32) ? im[y0*32 + x0]       : 0.f;
        float v10 = (x0+1 >= 0 && x0+1 < 32 && y0   >= 0 && y0   < 32) ? im[y0*32 + x0+1]     : 0.f;
        float v01 = (x0   >= 0 && x0   < 32 && y0+1 >= 0 && y0+1 < 32) ? im[(y0+1)*32 + x0]   : 0.f;
        float v11 = (x0+1 >= 0 && x0+1 < 32 && y0+1 >= 0 && y0+1 < 32) ? im[(y0+1)*32 + x0+1] : 0.f;
        As[c][p] = v00*(1.f-wx)*(1.f-wy) + v10*wx*(1.f-wy) + v01*(1.f-wx)*wy + v11*wx*wy;
    }
    __syncthreads();
    int tp = (t & 15) * 4, to = (t >> 4) * 4;
    float ak[4][4] = {}, av[4][4] = {};
    #pragma unroll
    for (int c = 0; c < 64; c += 4) {
        float4 a[4], wk[4], wv[4];
        #pragma unroll
        for (int u = 0; u < 4; u++) a[u] = *(const float4*)&As[c+u][tp];
        #pragma unroll
        for (int oi = 0; oi < 4; oi++) {
            wk[oi] = *(const float4*)&Wk[to+oi][c];
            wv[oi] = *(const float4*)&Wv[to+oi][c];
        }
        #pragma unroll
        for (int oi = 0; oi < 4; oi++) {
            float kf[4] = {wk[oi].x, wk[oi].y, wk[oi].z, wk[oi].w};
            float vf[4] = {wv[oi].x, wv[oi].y, wv[oi].z, wv[oi].w};
            #pragma unroll
            for (int u = 0; u < 4; u++) {
                ak[oi][0] += kf[u]*a[u].x; ak[oi][1] += kf[u]*a[u].y;
                ak[oi][2] += kf[u]*a[u].z; ak[oi][3] += kf[u]*a[u].w;
                av[oi][0] += vf[u]*a[u].x; av[oi][1] += vf[u]*a[u].y;
                av[oi][2] += vf[u]*a[u].z; av[oi][3] += vf[u]*a[u].w;
            }
        }
    }
    float* KO = kout + (size_t)bg*Cg*P;
    float* VO = vout + (size_t)bg*Cg*P;
    #pragma unroll
    for (int oi = 0; oi < 4; oi++)
        #pragma unroll
        for (int pj = 0; pj < 4; pj++) {
            KO[(to+oi)*P + tp+pj] = ak[oi][pj];
            VO[(to+oi)*P + tp+pj] = av[oi][pj];
        }
}

// ======================= fused attention (transposed bias read) =======================
__global__ __launch_bounds__(128, 1)
void attn_fused_kernel(const float* __restrict__ q, const float* __restrict__ k,
                       const float* __restrict__ v, const float* __restrict__ bias,
                       float* __restrict__ out) {
    extern __shared__ float sm[];
    float* att = sm;               // [128][65]
    float* ks  = att + 128*65;     // [64][64]
    float* vs  = ks + 64*64;       // [64][64]

    int t = threadIdx.x;
    int i0 = blockIdx.x * 128, bh = blockIdx.y;
    int b = bh >> 3, h = bh & 7;

    const float* kb = k + ((size_t)b*Cch + h*64)*P2;
    const float* vb = v + ((size_t)b*Cch + h*64)*P2;
    const float* qb = q + ((size_t)b*Cch + h*64)*Pp;
    const float* bb = bias + (size_t)bh*(P2*Pp);    // [j][i]
    float* ob = out + ((size_t)b*Cch + h*64)*Pp;

    for (int idx = t; idx < 4096; idx += 128) {
        ks[idx] = kb[idx];
        vs[idx] = vb[idx];
    }
    for (int idx = t; idx < 128*64; idx += 128) {
        int jj = idx >> 7, i = idx & 127;
        att[i*65 + jj] = bb[(size_t)jj*Pp + i0 + i];
    }
    float ql[64];
    #pragma unroll
    for (int d = 0; d < 64; d++) ql[d] = qb[d*Pp + i0 + t] * SCALE;
    __syncthreads();

    float* arow = att + t*65;
    float mx = -1e30f;
    #pragma unroll 2
    for (int jj = 0; jj < 64; jj++) {
        float s = arow[jj];
        #pragma unroll
        for (int d = 0; d < 64; d++) s += ql[d] * ks[d*64 + jj];
        arow[jj] = s;
        mx = fmaxf(mx, s);
    }
    float sum = 0.f;
    #pragma unroll 4
    for (int jj = 0; jj < 64; jj++) {
        float e = __expf(arow[jj] - mx);
        arow[jj] = e;
        sum += e;
    }
    float inv = 1.f / sum;

    int i = i0 + t;
    #pragma unroll
    for (int half = 0; half < 2; half++) {
        float o[32];
        #pragma unroll
        for (int d = 0; d < 32; d++) o[d] = 0.f;
        #pragma unroll 2
        for (int jj = 0; jj < 64; jj++) {
            float a = arow[jj];
            #pragma unroll
            for (int d = 0; d < 32; d++) o[d] += a * vs[(half*32 + d)*64 + jj];
        }
        #pragma unroll
        for (int d = 0; d < 32; d++) ob[(size_t)(half*32 + d)*Pp + i] = o[d] * inv;
    }
}

// ======================= tf32 GEMM — R7 proven version (static smem, sync staging) =======================
__device__ __forceinline__ uint32_t f2tf32(float v) {
    uint32_t u;
    asm("cvt.rna.tf32.f32 %0, %1;" : "=r"(u) : "f"(v));
    return u;
}
__device__ __forceinline__ void mma_tf32(float* c, const uint32_t* a, uint32_t b0, uint32_t b1) {
    asm volatile("mma.sync.aligned.m16n8k8.row.col.f32.tf32.tf32.f32 "
                 "{%0,%1,%2,%3}, {%4,%5,%6,%7}, {%8,%9}, {%0,%1,%2,%3};"
                 : "+f"(c[0]), "+f"(c[1]), "+f"(c[2]), "+f"(c[3])
                 : "r"(a[0]), "r"(a[1]), "r"(a[2]), "r"(a[3]), "r"(b0), "r"(b1));
}

__global__ __launch_bounds__(256)
void gemm_tf32_kernel(const float* __restrict__ A, const float* __restrict__ W,
                      const float* __restrict__ bias, const float* __restrict__ res,
                      float* __restrict__ out, int Cin, int act,
                      const float* __restrict__ bnsc, const float* __restrict__ bnsh) {
    const int P = 1024;
    int b = blockIdx.z;
    int O = gridDim.y * 128;
    int p0 = blockIdx.x * 128, o0 = blockIdx.y * 128;
    const float* Ab = A + (size_t)b*Cin*P;

    __shared__ float Wt[128][36];   // [o][c]
    __shared__ float Xt[32][136];   // [c][p]

    int t = threadIdx.x;
    int lane = t & 31, warp = t >> 5;
    int gid = lane >> 2, ctid = lane & 3;
    int m0w = (warp >> 1) * 32, n0w = (warp & 1) * 64;

    float c[2][8][4] = {};

    for (int cc = 0; cc < Cin; cc += 32) {
        __syncthreads();
        #pragma unroll
        for (int idx = t; idx < 1024; idx += 256) {
            int r = idx >> 3, q4 = (idx & 7) * 4;
            float4 wv = *(const float4*)&W[(size_t)(o0 + r)*Cin + cc + q4];
            *(float4*)&Wt[r][q4] = wv;
        }
        #pragma unroll
        for (int idx = t; idx < 1024; idx += 256) {
            int r = idx >> 5, q4 = (idx & 31) * 4;
            float4 xv = *(const float4*)&Ab[(size_t)(cc + r)*P + p0 + q4];
            if (bnsc) {
                float s = bnsc[cc + r], h = bnsh[cc + r];
                xv.x = fmaf(xv.x, s, h); xv.y = fmaf(xv.y, s, h);
                xv.z = fmaf(xv.z, s, h); xv.w = fmaf(xv.w, s, h);
            }
            *(float4*)&Xt[r][q4] = xv;
        }
        __syncthreads();
        #pragma unroll
        for (int k0 = 0; k0 < 32; k0 += 8) {
            uint32_t a[2][4];
            #pragma unroll
            for (int mt = 0; mt < 2; mt++) {
                int row = m0w + mt*16;
                a[mt][0] = f2tf32(Wt[row + gid    ][k0 + ctid]);
                a[mt][1] = f2tf32(Wt[row + 8 + gid][k0 + ctid]);
                a[mt][2] = f2tf32(Wt[row + gid    ][k0 + ctid + 4]);
                a[mt][3] = f2tf32(Wt[row + 8 + gid][k0 + ctid + 4]);
            }
            #pragma unroll
            for (int nt = 0; nt < 8; nt++) {
                int n = n0w + nt*8 + gid;
                uint32_t b0v = f2tf32(Xt[k0 + ctid    ][n]);
                uint32_t b1v = f2tf32(Xt[k0 + ctid + 4][n]);
                mma_tf32(c[0][nt], a[0], b0v, b1v);
                mma_tf32(c[1][nt], a[1], b0v, b1v);
            }
        }
    }

    float* ob = out + (size_t)b*O*P;
    const float* rb = res ? res + (size_t)b*O*P : nullptr;
    #pragma unroll
    for (int mt = 0; mt < 2; mt++) {
        #pragma unroll
        for (int half = 0; half < 2; half++) {
            int o = o0 + m0w + mt*16 + gid + half*8;
            float bv = bias[o];
            #pragma unroll
            for (int nt = 0; nt < 8; nt++) {
                int p = p0 + n0w + nt*8 + 2*ctid;
                float v0 = c[mt][nt][half*2+0] + bv;
                float v1 = c[mt][nt][half*2+1] + bv;
                if (act == 1) {
                    v0 = 0.5f * v0 * (1.f + erff(v0 * 0.70710678118654752f));
                    v1 = 0.5f * v1 * (1.f + erff(v1 * 0.70710678118654752f));
                }
                if (rb) {
                    const float2 rv = *(const float2*)&rb[(size_t)o*P + p];
                    v0 += rv.x; v1 += rv.y;
                }
                float2 st; st.x = v0; st.y = v1;
                *(float2*)&ob[(size_t)o*P + p] = st;
            }
        }
    }
}

// ---------------- launch ----------------
extern "C" void kernel_launch(void* const* d_in, const int* in_sizes, int n_in,
                              void* d_out, int out_size) {
    const float* x        = (const float*)d_in[0];
    const float* n1_g     = (const float*)d_in[1];
    const float* n1_b     = (const float*)d_in[2];
    const float* n2_g     = (const float*)d_in[3];
    const float* n2_b     = (const float*)d_in[4];
    const float* q_w      = (const float*)d_in[5];
    const float* k_w      = (const float*)d_in[6];
    const float* v_w      = (const float*)d_in[7];
    const float* off_dw_w = (const float*)d_in[8];
    const float* off_dw_b = (const float*)d_in[9];
    const float* off_pw_w = (const float*)d_in[10];
    const float* cpb_w0   = (const float*)d_in[11];
    const float* cpb_b0   = (const float*)d_in[12];
    const float* cpb_w1   = (const float*)d_in[13];
    const float* cpb_b1   = (const float*)d_in[14];
    const float* cpb_w2   = (const float*)d_in[15];
    const float* cpb_b2   = (const float*)d_in[16];
    const float* out_w    = (const float*)d_in[17];
    const float* out_b    = (const float*)d_in[18];
    const float* mlp_w1   = (const float*)d_in[19];
    const float* mlp_b1   = (const float*)d_in[20];
    const float* mlp_w2   = (const float*)d_in[21];
    const float* mlp_b2   = (const float*)d_in[22];
    float* out = (float*)d_out;

    float *p_xn, *p_q, *p_grid, *p_k, *p_v, *p_bias, *p_ao, *p_x1, *p_m1, *p_sc, *p_sh;
    cudaGetSymbolAddress((void**)&p_xn,   g_xn);
    cudaGetSymbolAddress((void**)&p_q,    g_q);
    cudaGetSymbolAddress((void**)&p_grid, g_grid);
    cudaGetSymbolAddress((void**)&p_k,    g_k);
    cudaGetSymbolAddress((void**)&p_v,    g_v);
    cudaGetSymbolAddress((void**)&p_bias, g_bias);
    cudaGetSymbolAddress((void**)&p_ao,   g_ao);
    cudaGetSymbolAddress((void**)&p_x1,   g_x1);
    cudaGetSymbolAddress((void**)&p_m1,   g_m1);
    cudaGetSymbolAddress((void**)&p_sc,   g_bnsc);
    cudaGetSymbolAddress((void**)&p_sh,   g_bnsh);

    // 1. batchnorm1
    bn_kernel<<<512, 256>>>(x, n1_g, n1_b, p_xn);
    // 2. q grouped conv
    gconv_kernel<<<dim3(16, 16), 256>>>(p_xn, q_w, p_q, Pp);
    // 3. fused dwconv+gelu -> offsets -> grid
    dwoff_kernel<<<16, 512>>>(p_q, off_dw_w, off_dw_b, off_pw_w, p_grid);
    // 4. CPB bias MLP  <-- should land in ncu's capture slot
    {
        int smem = 3*128*BPAD*2 + (256 + 128 + 128 + 128)*4;
        cudaFuncSetAttribute(bias_mma_kernel, cudaFuncAttributeMaxDynamicSharedMemorySize, smem);
        bias_mma_kernel<<<dim3(32, 16), 256, smem>>>(p_grid, cpb_w0, cpb_b0, cpb_w1, cpb_b1,
                                                     cpb_w2, cpb_b2, p_bias);
    }
    // 5. k + v grouped convs with inline bilinear sampling
    gconv_kv_kernel<<<16, 256>>>(p_xn, p_grid, k_w, v_w, p_k, p_v);
    // 6. fused attention
    {
        int smem = (128*65 + 64*64 + 64*64) * 4;
        cudaFuncSetAttribute(attn_fused_kernel, cudaFuncAttributeMaxDynamicSharedMemorySize, smem);
        attn_fused_kernel<<<dim3(8, 16), 128, smem>>>(p_q, p_k, p_v, p_bias, p_ao);
    }
    // 7. out projection + residual
    gemm_tf32_kernel<<<dim3(8, 4, 2), 256>>>(p_ao, out_w, out_b, x, p_x1, 512, 0, nullptr, nullptr);
    // 8. batchnorm2 stats
    bn_stats_kernel<<<512, 256>>>(p_x1, n2_g, n2_b, p_sc, p_sh);
    // 9. mlp1 + gelu (bn2 affine fused in staging)
    gemm_tf32_kernel<<<dim3(8, 16, 2), 256>>>(p_x1, mlp_w1, mlp_b1, nullptr, p_m1, 512, 1, p_sc, p_sh);
    // 10. mlp2 + residual
    gemm_tf32_kernel<<<dim3(8, 4, 2), 256>>>(p_m1, mlp_w2, mlp_b2, p_x1, out, 2048, 0, nullptr, nullptr);
}

// round 12
// speedup vs baseline: 1.5543x; 1.0919x over previous
#include <cuda_runtime.h>
#include <cuda_bf16.h>
#include <stdint.h>
#include <math.h>

// Problem constants
#define Bsz 2
#define Cch 512
#define Gg  8
#define Cg  64
#define Pp  1024          // H*W
#define P2  64            // H2*W2
#define SCALE 0.125f

// ---------------- scratch ----------------
__device__ float g_xn  [Bsz*Cch*Pp];
__device__ float g_q   [Bsz*Cch*Pp];
__device__ float g_grid[16*P2*2];
__device__ float g_k   [Bsz*Cch*P2];
__device__ float g_v   [Bsz*Cch*P2];
__device__ float g_bias[16*P2*Pp];       // [bg][j][i]
__device__ float g_ao  [Bsz*Cch*Pp];
__device__ float g_x1  [Bsz*Cch*Pp];
__device__ float g_m1  [Bsz*2048*Pp];
__device__ float g_bnsc[Cch];
__device__ float g_bnsh[Cch];

// ---------------- batchnorm (full) ----------------
__global__ void bn_kernel(const float* __restrict__ x, const float* __restrict__ g,
                          const float* __restrict__ b, float* __restrict__ y) {
    int c = blockIdx.x, t = threadIdx.x;
    __shared__ float ssum[256], ssq[256];
    float s = 0.f, q = 0.f;
    for (int idx = t; idx < 2048; idx += 256) {
        int bb = idx >> 10, p = idx & 1023;
        float v = x[bb*(Cch*Pp) + c*Pp + p];
        s += v; q += v*v;
    }
    ssum[t] = s; ssq[t] = q; __syncthreads();
    for (int o = 128; o > 0; o >>= 1) {
        if (t < o) { ssum[t] += ssum[t+o]; ssq[t] += ssq[t+o]; }
        __syncthreads();
    }
    float m  = ssum[0] * (1.f/2048.f);
    float var = ssq[0] * (1.f/2048.f) - m*m;
    float rs = rsqrtf(var + 1e-5f);
    float gg = g[c] * rs;
    float bb2 = b[c] - m * gg;
    for (int idx = t; idx < 2048; idx += 256) {
        int bb = idx >> 10, p = idx & 1023;
        y[bb*(Cch*Pp) + c*Pp + p] = x[bb*(Cch*Pp) + c*Pp + p] * gg + bb2;
    }
}

// ---------------- batchnorm stats only ----------------
__global__ void bn_stats_kernel(const float* __restrict__ x, const float* __restrict__ g,
                                const float* __restrict__ b, float* __restrict__ sc,
                                float* __restrict__ sh) {
    int c = blockIdx.x, t = threadIdx.x;
    __shared__ float ssum[256], ssq[256];
    float s = 0.f, q = 0.f;
    for (int idx = t; idx < 2048; idx += 256) {
        int bb = idx >> 10, p = idx & 1023;
        float v = x[bb*(Cch*Pp) + c*Pp + p];
        s += v; q += v*v;
    }
    ssum[t] = s; ssq[t] = q; __syncthreads();
    for (int o = 128; o > 0; o >>= 1) {
        if (t < o) { ssum[t] += ssum[t+o]; ssq[t] += ssq[t+o]; }
        __syncthreads();
    }
    if (t == 0) {
        float m  = ssum[0] * (1.f/2048.f);
        float var = ssq[0] * (1.f/2048.f) - m*m;
        float rs = rsqrtf(var + 1e-5f);
        float gg = g[c] * rs;
        sc[c] = gg;
        sh[c] = b[c] - m * gg;
    }
}

// ---------------- grouped 1x1 conv (q) ----------------
__global__ void gconv_kernel(const float* __restrict__ in, const float* __restrict__ w,
                             float* __restrict__ out, int P) {
    int bg = blockIdx.x, pt = blockIdx.y;
    int grp = bg & 7;
    const float* A  = in + (size_t)bg*Cg*P + pt*64;
    const float* Wg = w + grp*4096;
    float* O        = out + (size_t)bg*Cg*P + pt*64;
    __shared__ float As[64][64];
    __shared__ float Ws[64][64];
    int t = threadIdx.x;
    for (int idx = t; idx < 4096; idx += 256) {
        int r = idx >> 6, q = idx & 63;
        As[r][q] = A[r*P + q];
        ((float*)Ws)[idx] = Wg[idx];
    }
    __syncthreads();
    int tp = (t & 15) * 4, to = (t >> 4) * 4;
    float acc[4][4] = {};
    #pragma unroll
    for (int c = 0; c < 64; c += 4) {
        float4 a[4], wv[4];
        #pragma unroll
        for (int u = 0; u < 4; u++) a[u] = *(const float4*)&As[c+u][tp];
        #pragma unroll
        for (int oi = 0; oi < 4; oi++) wv[oi] = *(const float4*)&Ws[to+oi][c];
        #pragma unroll
        for (int oi = 0; oi < 4; oi++) {
            float wf[4] = {wv[oi].x, wv[oi].y, wv[oi].z, wv[oi].w};
            #pragma unroll
            for (int u = 0; u < 4; u++) {
                acc[oi][0] += wf[u]*a[u].x; acc[oi][1] += wf[u]*a[u].y;
                acc[oi][2] += wf[u]*a[u].z; acc[oi][3] += wf[u]*a[u].w;
            }
        }
    }
    #pragma unroll
    for (int oi = 0; oi < 4; oi++)
        #pragma unroll
        for (int pj = 0; pj < 4; pj++)
            O[(to+oi)*P + tp+pj] = acc[oi][pj];
}

// ---------------- fused depthwise conv+gelu -> pointwise offsets -> grid ----------------
__global__ void dwoff_kernel(const float* __restrict__ q, const float* __restrict__ dw,
                             const float* __restrict__ db, const float* __restrict__ pw,
                             float* __restrict__ grid) {
    __shared__ float off1s[Cg*P2];
    __shared__ float part[2][8][64];
    int bg = blockIdx.x, t = threadIdx.x;

    for (int idx = t; idx < Cg*P2; idx += 512) {
        int p = idx & 63, c = idx >> 6;
        int oy = p >> 3, ox = p & 7;
        float acc = db[c];
        const float* ip = q + (size_t)bg*Cg*Pp + c*Pp;
        const float* wp = dw + c*36;
        #pragma unroll
        for (int ky = 0; ky < 6; ky++) {
            int iy = oy*4 - 1 + ky;
            if (iy < 0 || iy >= 32) continue;
            #pragma unroll
            for (int kx = 0; kx < 6; kx++) {
                int ix = ox*4 - 1 + kx;
                if (ix < 0 || ix >= 32) continue;
                acc += ip[iy*32 + ix] * wp[ky*6 + kx];
            }
        }
        off1s[idx] = 0.5f * acc * (1.f + erff(acc * 0.70710678118654752f));
    }
    __syncthreads();

    int qd = t >> 6, p = t & 63;
    float s0 = 0.f, s1 = 0.f;
    #pragma unroll
    for (int cc = 0; cc < 8; cc++) {
        int c = qd*8 + cc;
        float v = off1s[c*64 + p];
        s0 = fmaf(v, pw[c], s0);
        s1 = fmaf(v, pw[64 + c], s1);
    }
    part[0][qd][p] = s0;
    part[1][qd][p] = s1;
    __syncthreads();
    if (t < 64) {
        float t0 = 0.f, t1 = 0.f;
        #pragma unroll
        for (int u = 0; u < 8; u++) { t0 += part[0][u][t]; t1 += part[1][u][t]; }
        float ox = tanhf(t0) * 4.f, oy = tanhf(t1) * 4.f;
        float gx = (float)(t & 7), gy = (float)(t >> 3);
        grid[bg*128 + t*2]   = 2.f * (gx + ox) * (1.f/7.f) - 1.f;
        grid[bg*128 + t*2+1] = 2.f * (gy + oy) * (1.f/7.f) - 1.f;
    }
}

// ======================= CPB bias MLP — HMMA, B-persistent in registers =======================
#define BPAD 136   // bf16 row stride (halfs); 272B = 16B-aligned

__device__ __forceinline__ void ldsm4(uint32_t addr, uint32_t& r0, uint32_t& r1,
                                      uint32_t& r2, uint32_t& r3) {
    asm volatile("ldmatrix.sync.aligned.m8n8.x4.shared.b16 {%0,%1,%2,%3}, [%4];"
                 : "=r"(r0), "=r"(r1), "=r"(r2), "=r"(r3) : "r"(addr));
}
__device__ __forceinline__ void mma_bf16(float* c, const uint32_t* a, uint32_t b0, uint32_t b1) {
    asm volatile("mma.sync.aligned.m16n8k16.row.col.f32.bf16.bf16.f32 "
                 "{%0,%1,%2,%3}, {%4,%5,%6,%7}, {%8,%9}, {%0,%1,%2,%3};"
                 : "+f"(c[0]), "+f"(c[1]), "+f"(c[2]), "+f"(c[3])
                 : "r"(a[0]), "r"(a[1]), "r"(a[2]), "r"(a[3]), "r"(b0), "r"(b1));
}

// block: 128 thr (4 warps), one j. warp owns n-quarter [warp*32, warp*32+32).
// B-frags persistent in regs. i-tile of 128 rows processed in 2 sub-tiles of 64.
__global__ __launch_bounds__(128)
void bias_mma_kernel(const float* __restrict__ grid,
                     const float* __restrict__ w0, const float* __restrict__ b0,
                     const float* __restrict__ w1, const float* __restrict__ b1,
                     const float* __restrict__ w2, const float* __restrict__ b2,
                     float* __restrict__ bias) {
    extern __shared__ unsigned char smraw[];
    __nv_bfloat16* W1Ts = (__nv_bfloat16*)smraw;            // [n][s] 128 x BPAD (init only)
    __nv_bfloat16* H1s  = W1Ts + 128*BPAD;                  // [i][s] 128 x BPAD
    float* w0s  = (float*)(H1s + 128*BPAD);                 // 256
    float* b0s  = w0s + 256;                                // 128
    float* b1s  = b0s + 128;                                // 128
    float* w2s  = b1s + 128;                                // 128
    float* part = w2s + 128;                                // 4 x 72

    int t = threadIdx.x;
    int lane = t & 31, warp = t >> 5;
    int j = blockIdx.x, bg = blockIdx.y;

    // stage W1^T (for one-time B-frag load)
    for (int idx = t; idx < 16384; idx += 128) {
        int s = idx >> 7, n = idx & 127;
        W1Ts[n*BPAD + s] = __float2bfloat16(w1[idx]);
    }
    for (int idx = t; idx < 256; idx += 128) w0s[idx] = w0[idx];
    b0s[t] = b0[t];
    b1s[t] = b1[t];
    w2s[t] = w2[t];
    float kvx = grid[bg*128 + j*2], kvy = grid[bg*128 + j*2 + 1];
    float b2v = b2[0];
    __syncthreads();

    uint32_t h1base = (uint32_t)__cvta_generic_to_shared(H1s);
    uint32_t w1base = (uint32_t)__cvta_generic_to_shared(W1Ts);

    // lane mappings (identical to proven R9 layout)
    int arow  = (lane & 7) + ((lane >> 3) & 1) * 8;
    int acolq = (lane >> 4) * 8;
    int bn_off = (lane >> 4) * 8 + (lane & 7);
    int bcol   = ((lane >> 3) & 1) * 8;
    int gid = lane >> 2, ctid = lane & 3;

    // one-time persistent B-frag load: warp's n-range = [warp*32, warp*32+32)
    uint32_t Breg[2][8][4];
    #pragma unroll
    for (int np = 0; np < 2; np++) {
        int n = warp*32 + np*16 + bn_off;
        #pragma unroll
        for (int k8 = 0; k8 < 8; k8++) {
            uint32_t addr = w1base + (uint32_t)(n*BPAD + k8*16 + bcol) * 2u;
            ldsm4(addr, Breg[np][k8][0], Breg[np][k8][1], Breg[np][k8][2], Breg[np][k8][3]);
        }
    }
    // b1/w2 values for this warp's columns (per nt): n = warp*32 + nt*8 + 2*ctid
    float b1r[4][2], w2r[4][2];
    #pragma unroll
    for (int nt = 0; nt < 4; nt++) {
        int n = warp*32 + nt*8 + 2*ctid;
        b1r[nt][0] = b1s[n];   b1r[nt][1] = b1s[n+1];
        w2r[nt][0] = w2s[n];   w2r[nt][1] = w2s[n+1];
    }

    float* brow = bias + (size_t)bg*(P2*Pp) + (size_t)j*Pp;

    for (int it = 0; it < 8; it++) {
        int i0 = it*128;
        // build H1 row t (16 x STS.128)
        {
            int i = i0 + t;
            float qx = 2.f * (float)(i & 31) * (1.f/31.f) - 1.f;
            float qy = 2.f * (float)(i >> 5) * (1.f/31.f) - 1.f;
            float px = qx - kvx, py = qy - kvy;
            float fx = copysignf(log1pf(fabsf(px)), px);
            float fy = copysignf(log1pf(fabsf(py)), py);
            uint32_t rowb = (uint32_t)(t*BPAD) * 2u;
            #pragma unroll
            for (int c8 = 0; c8 < 16; c8++) {
                uint32_t u[4];
                #pragma unroll
                for (int e = 0; e < 4; e++) {
                    int s = c8*8 + e*2;
                    float h0 = fmaxf(fmaf(fy, w0s[128+s],   fmaf(fx, w0s[s],   b0s[s])),   0.f);
                    float h1 = fmaxf(fmaf(fy, w0s[128+s+1], fmaf(fx, w0s[s+1], b0s[s+1])), 0.f);
                    __nv_bfloat162 pr = __floats2bfloat162_rn(h0, h1);
                    u[e] = *(uint32_t*)&pr;
                }
                *(uint4*)((char*)H1s + rowb + c8*16) = make_uint4(u[0], u[1], u[2], u[3]);
            }
        }
        __syncthreads();

        #pragma unroll
        for (int sub = 0; sub < 2; sub++) {
            int r0 = sub*64;
            float c[4][4][4];
            #pragma unroll
            for (int mt = 0; mt < 4; mt++)
                #pragma unroll
                for (int nt = 0; nt < 4; nt++)
                    #pragma unroll
                    for (int f = 0; f < 4; f++) c[mt][nt][f] = 0.f;

            #pragma unroll
            for (int k8 = 0; k8 < 8; k8++) {
                uint32_t A[4][4];
                #pragma unroll
                for (int mt = 0; mt < 4; mt++) {
                    int row = r0 + mt*16 + arow;
                    uint32_t addr = h1base + (uint32_t)(row*BPAD + k8*16 + acolq) * 2u;
                    ldsm4(addr, A[mt][0], A[mt][1], A[mt][2], A[mt][3]);
                }
                #pragma unroll
                for (int nt = 0; nt < 4; nt++) {
                    uint32_t bb0 = Breg[nt>>1][k8][(nt&1)*2];
                    uint32_t bb1 = Breg[nt>>1][k8][(nt&1)*2+1];
                    #pragma unroll
                    for (int mt = 0; mt < 4; mt++)
                        mma_bf16(c[mt][nt], A[mt], bb0, bb1);
                }
            }

            // epilogue: per-lane partial over warp's 32 n's
            #pragma unroll
            for (int mt = 0; mt < 4; mt++) {
                float v0 = 0.f, v1 = 0.f;
                #pragma unroll
                for (int nt = 0; nt < 4; nt++) {
                    v0 += fmaxf(c[mt][nt][0]+b1r[nt][0], 0.f)*w2r[nt][0]
                        + fmaxf(c[mt][nt][1]+b1r[nt][1], 0.f)*w2r[nt][1];
                    v1 += fmaxf(c[mt][nt][2]+b1r[nt][0], 0.f)*w2r[nt][0]
                        + fmaxf(c[mt][nt][3]+b1r[nt][1], 0.f)*w2r[nt][1];
                }
                v0 += __shfl_xor_sync(0xffffffffu, v0, 1);
                v0 += __shfl_xor_sync(0xffffffffu, v0, 2);
                v1 += __shfl_xor_sync(0xffffffffu, v1, 1);
                v1 += __shfl_xor_sync(0xffffffffu, v1, 2);
                if (ctid == 0) {
                    part[warp*72 + mt*16 + gid]     = v0;
                    part[warp*72 + mt*16 + gid + 8] = v1;
                }
            }
            __syncthreads();
            if (t < 64) {
                float sum = part[t] + part[72 + t] + part[144 + t] + part[216 + t];
                brow[i0 + r0 + t] = sum + b2v;
            }
            __syncthreads();
        }
    }
}

// ---------------- gconv k,v with inline bilinear sampling ----------------
__global__ void gconv_kv_kernel(const float* __restrict__ xn, const float* __restrict__ grid,
                                const float* __restrict__ kw, const float* __restrict__ vw,
                                float* __restrict__ kout, float* __restrict__ vout) {
    const int P = P2;
    int bg = blockIdx.x;
    int grp = bg & 7;
    __shared__ float sgrid[128];
    __shared__ float As[64][64];
    __shared__ float Wk[64][64];
    __shared__ float Wv[64][64];
    int t = threadIdx.x;
    if (t < 128) sgrid[t] = grid[bg*128 + t];
    for (int idx = t; idx < 4096; idx += 256) {
        ((float*)Wk)[idx] = kw[grp*4096 + idx];
        ((float*)Wv)[idx] = vw[grp*4096 + idx];
    }
    __syncthreads();
    for (int idx = t; idx < 4096; idx += 256) {
        int p = idx & 63, c = idx >> 6;
        float vx = sgrid[p*2], vy = sgrid[p*2+1];
        float x = ((vx + 1.f) * 32.f - 1.f) * 0.5f;
        float y = ((vy + 1.f) * 32.f - 1.f) * 0.5f;
        float x0f = floorf(x), y0f = floorf(y);
        int x0 = (int)x0f, y0 = (int)y0f;
        float wx = x - x0f, wy = y - y0f;
        const float* im = xn + (size_t)bg*Cg*Pp + c*Pp;
        float v00 = (x0   >= 0 && x0   < 32 && y0   >= 0 && y0   < 32) ? im[y0*32 + x0]       : 0.f;
        float v10 = (x0+1 >= 0 && x0+1 < 32 && y0   >= 0 && y0   < 32) ? im[y0*32 + x0+1]     : 0.f;
        float v01 = (x0   >= 0 && x0   < 32 && y0+1 >= 0 && y0+1 < 32) ? im[(y0+1)*32 + x0]   : 0.f;
        float v11 = (x0+1 >= 0 && x0+1 < 32 && y0+1 >= 0 && y0+1 < 32) ? im[(y0+1)*32 + x0+1] : 0.f;
        As[c][p] = v00*(1.f-wx)*(1.f-wy) + v10*wx*(1.f-wy) + v01*(1.f-wx)*wy + v11*wx*wy;
    }
    __syncthreads();
    int tp = (t & 15) * 4, to = (t >> 4) * 4;
    float ak[4][4] = {}, av[4][4] = {};
    #pragma unroll
    for (int c = 0; c < 64; c += 4) {
        float4 a[4], wk[4], wv[4];
        #pragma unroll
        for (int u = 0; u < 4; u++) a[u] = *(const float4*)&As[c+u][tp];
        #pragma unroll
        for (int oi = 0; oi < 4; oi++) {
            wk[oi] = *(const float4*)&Wk[to+oi][c];
            wv[oi] = *(const float4*)&Wv[to+oi][c];
        }
        #pragma unroll
        for (int oi = 0; oi < 4; oi++) {
            float kf[4] = {wk[oi].x, wk[oi].y, wk[oi].z, wk[oi].w};
            float vf[4] = {wv[oi].x, wv[oi].y, wv[oi].z, wv[oi].w};
            #pragma unroll
            for (int u = 0; u < 4; u++) {
                ak[oi][0] += kf[u]*a[u].x; ak[oi][1] += kf[u]*a[u].y;
                ak[oi][2] += kf[u]*a[u].z; ak[oi][3] += kf[u]*a[u].w;
                av[oi][0] += vf[u]*a[u].x; av[oi][1] += vf[u]*a[u].y;
                av[oi][2] += vf[u]*a[u].z; av[oi][3] += vf[u]*a[u].w;
            }
        }
    }
    float* KO = kout + (size_t)bg*Cg*P;
    float* VO = vout + (size_t)bg*Cg*P;
    #pragma unroll
    for (int oi = 0; oi < 4; oi++)
        #pragma unroll
        for (int pj = 0; pj < 4; pj++) {
            KO[(to+oi)*P + tp+pj] = ak[oi][pj];
            VO[(to+oi)*P + tp+pj] = av[oi][pj];
        }
}

// ======================= fused attention (transposed bias read) =======================
__global__ __launch_bounds__(128, 1)
void attn_fused_kernel(const float* __restrict__ q, const float* __restrict__ k,
                       const float* __restrict__ v, const float* __restrict__ bias,
                       float* __restrict__ out) {
    extern __shared__ float sm[];
    float* att = sm;               // [128][65]
    float* ks  = att + 128*65;     // [64][64]
    float* vs  = ks + 64*64;       // [64][64]

    int t = threadIdx.x;
    int i0 = blockIdx.x * 128, bh = blockIdx.y;
    int b = bh >> 3, h = bh & 7;

    const float* kb = k + ((size_t)b*Cch + h*64)*P2;
    const float* vb = v + ((size_t)b*Cch + h*64)*P2;
    const float* qb = q + ((size_t)b*Cch + h*64)*Pp;
    const float* bb = bias + (size_t)bh*(P2*Pp);    // [j][i]
    float* ob = out + ((size_t)b*Cch + h*64)*Pp;

    for (int idx = t; idx < 4096; idx += 128) {
        ks[idx] = kb[idx];
        vs[idx] = vb[idx];
    }
    for (int idx = t; idx < 128*64; idx += 128) {
        int jj = idx >> 7, i = idx & 127;
        att[i*65 + jj] = bb[(size_t)jj*Pp + i0 + i];
    }
    float ql[64];
    #pragma unroll
    for (int d = 0; d < 64; d++) ql[d] = qb[d*Pp + i0 + t] * SCALE;
    __syncthreads();

    float* arow = att + t*65;
    float mx = -1e30f;
    #pragma unroll 2
    for (int jj = 0; jj < 64; jj++) {
        float s = arow[jj];
        #pragma unroll
        for (int d = 0; d < 64; d++) s += ql[d] * ks[d*64 + jj];
        arow[jj] = s;
        mx = fmaxf(mx, s);
    }
    float sum = 0.f;
    #pragma unroll 4
    for (int jj = 0; jj < 64; jj++) {
        float e = __expf(arow[jj] - mx);
        arow[jj] = e;
        sum += e;
    }
    float inv = 1.f / sum;

    int i = i0 + t;
    #pragma unroll
    for (int half = 0; half < 2; half++) {
        float o[32];
        #pragma unroll
        for (int d = 0; d < 32; d++) o[d] = 0.f;
        #pragma unroll 2
        for (int jj = 0; jj < 64; jj++) {
            float a = arow[jj];
            #pragma unroll
            for (int d = 0; d < 32; d++) o[d] += a * vs[(half*32 + d)*64 + jj];
        }
        #pragma unroll
        for (int d = 0; d < 32; d++) ob[(size_t)(half*32 + d)*Pp + i] = o[d] * inv;
    }
}

// ======================= tf32 GEMM — templated p-tile =======================
__device__ __forceinline__ uint32_t f2tf32(float v) {
    uint32_t u;
    asm("cvt.rna.tf32.f32 %0, %1;" : "=r"(u) : "f"(v));
    return u;
}
__device__ __forceinline__ void mma_tf32(float* c, const uint32_t* a, uint32_t b0, uint32_t b1) {
    asm volatile("mma.sync.aligned.m16n8k8.row.col.f32.tf32.tf32.f32 "
                 "{%0,%1,%2,%3}, {%4,%5,%6,%7}, {%8,%9}, {%0,%1,%2,%3};"
                 : "+f"(c[0]), "+f"(c[1]), "+f"(c[2]), "+f"(c[3])
                 : "r"(a[0]), "r"(a[1]), "r"(a[2]), "r"(a[3]), "r"(b0), "r"(b1));
}

// PT = p-tile width (64 or 128). block 256 thr, o-tile 128.
template<int PT>
__global__ __launch_bounds__(256)
void gemm_tf32_kernel(const float* __restrict__ A, const float* __restrict__ W,
                      const float* __restrict__ bias, const float* __restrict__ res,
                      float* __restrict__ out, int Cin, int act,
                      const float* __restrict__ bnsc, const float* __restrict__ bnsh) {
    const int P = 1024;
    const int NT = PT / 16;            // n-tiles per warp
    int b = blockIdx.z;
    int O = gridDim.y * 128;
    int p0 = blockIdx.x * PT, o0 = blockIdx.y * 128;
    const float* Ab = A + (size_t)b*Cin*P;

    __shared__ float Wt[128][36];      // [o][c]
    __shared__ float Xt[32][PT + 8];   // [c][p]

    int t = threadIdx.x;
    int lane = t & 31, warp = t >> 5;
    int gid = lane >> 2, ctid = lane & 3;
    int m0w = (warp >> 1) * 32, n0w = (warp & 1) * (PT/2);

    float c[2][NT][4];
    #pragma unroll
    for (int mt = 0; mt < 2; mt++)
        #pragma unroll
        for (int nt = 0; nt < NT; nt++)
            #pragma unroll
            for (int f = 0; f < 4; f++) c[mt][nt][f] = 0.f;

    for (int cc = 0; cc < Cin; cc += 32) {
        __syncthreads();
        #pragma unroll
        for (int idx = t; idx < 1024; idx += 256) {
            int r = idx >> 3, q4 = (idx & 7) * 4;
            float4 wv = *(const float4*)&W[(size_t)(o0 + r)*Cin + cc + q4];
            *(float4*)&Wt[r][q4] = wv;
        }
        #pragma unroll
        for (int idx = t; idx < 32*(PT/4); idx += 256) {
            int r = idx / (PT/4), q4 = (idx % (PT/4)) * 4;
            float4 xv = *(const float4*)&Ab[(size_t)(cc + r)*P + p0 + q4];
            if (bnsc) {
                float s = bnsc[cc + r], h = bnsh[cc + r];
                xv.x = fmaf(xv.x, s, h); xv.y = fmaf(xv.y, s, h);
                xv.z = fmaf(xv.z, s, h); xv.w = fmaf(xv.w, s, h);
            }
            *(float4*)&Xt[r][q4] = xv;
        }
        __syncthreads();
        #pragma unroll
        for (int k0 = 0; k0 < 32; k0 += 8) {
            uint32_t a[2][4];
            #pragma unroll
            for (int mt = 0; mt < 2; mt++) {
                int row = m0w + mt*16;
                a[mt][0] = f2tf32(Wt[row + gid    ][k0 + ctid]);
                a[mt][1] = f2tf32(Wt[row + 8 + gid][k0 + ctid]);
                a[mt][2] = f2tf32(Wt[row + gid    ][k0 + ctid + 4]);
                a[mt][3] = f2tf32(Wt[row + 8 + gid][k0 + ctid + 4]);
            }
            #pragma unroll
            for (int nt = 0; nt < NT; nt++) {
                int n = n0w + nt*8 + gid;
                uint32_t b0v = f2tf32(Xt[k0 + ctid    ][n]);
                uint32_t b1v = f2tf32(Xt[k0 + ctid + 4][n]);
                mma_tf32(c[0][nt], a[0], b0v, b1v);
                mma_tf32(c[1][nt], a[1], b0v, b1v);
            }
        }
    }

    float* ob = out + (size_t)b*O*P;
    const float* rb = res ? res + (size_t)b*O*P : nullptr;
    #pragma unroll
    for (int mt = 0; mt < 2; mt++) {
        #pragma unroll
        for (int half = 0; half < 2; half++) {
            int o = o0 + m0w + mt*16 + gid + half*8;
            float bv = bias[o];
            #pragma unroll
            for (int nt = 0; nt < NT; nt++) {
                int p = p0 + n0w + nt*8 + 2*ctid;
                float v0 = c[mt][nt][half*2+0] + bv;
                float v1 = c[mt][nt][half*2+1] + bv;
                if (act == 1) {
                    v0 = 0.5f * v0 * (1.f + erff(v0 * 0.70710678118654752f));
                    v1 = 0.5f * v1 * (1.f + erff(v1 * 0.70710678118654752f));
                }
                if (rb) {
                    const float2 rv = *(const float2*)&rb[(size_t)o*P + p];
                    v0 += rv.x; v1 += rv.y;
                }
                float2 st; st.x = v0; st.y = v1;
                *(float2*)&ob[(size_t)o*P + p] = st;
            }
        }
    }
}

// ---------------- launch ----------------
extern "C" void kernel_launch(void* const* d_in, const int* in_sizes, int n_in,
                              void* d_out, int out_size) {
    const float* x        = (const float*)d_in[0];
    const float* n1_g     = (const float*)d_in[1];
    const float* n1_b     = (const float*)d_in[2];
    const float* n2_g     = (const float*)d_in[3];
    const float* n2_b     = (const float*)d_in[4];
    const float* q_w      = (const float*)d_in[5];
    const float* k_w      = (const float*)d_in[6];
    const float* v_w      = (const float*)d_in[7];
    const float* off_dw_w = (const float*)d_in[8];
    const float* off_dw_b = (const float*)d_in[9];
    const float* off_pw_w = (const float*)d_in[10];
    const float* cpb_w0   = (const float*)d_in[11];
    const float* cpb_b0   = (const float*)d_in[12];
    const float* cpb_w1   = (const float*)d_in[13];
    const float* cpb_b1   = (const float*)d_in[14];
    const float* cpb_w2   = (const float*)d_in[15];
    const float* cpb_b2   = (const float*)d_in[16];
    const float* out_w    = (const float*)d_in[17];
    const float* out_b    = (const float*)d_in[18];
    const float* mlp_w1   = (const float*)d_in[19];
    const float* mlp_b1   = (const float*)d_in[20];
    const float* mlp_w2   = (const float*)d_in[21];
    const float* mlp_b2   = (const float*)d_in[22];
    float* out = (float*)d_out;

    float *p_xn, *p_q, *p_grid, *p_k, *p_v, *p_bias, *p_ao, *p_x1, *p_m1, *p_sc, *p_sh;
    cudaGetSymbolAddress((void**)&p_xn,   g_xn);
    cudaGetSymbolAddress((void**)&p_q,    g_q);
    cudaGetSymbolAddress((void**)&p_grid, g_grid);
    cudaGetSymbolAddress((void**)&p_k,    g_k);
    cudaGetSymbolAddress((void**)&p_v,    g_v);
    cudaGetSymbolAddress((void**)&p_bias, g_bias);
    cudaGetSymbolAddress((void**)&p_ao,   g_ao);
    cudaGetSymbolAddress((void**)&p_x1,   g_x1);
    cudaGetSymbolAddress((void**)&p_m1,   g_m1);
    cudaGetSymbolAddress((void**)&p_sc,   g_bnsc);
    cudaGetSymbolAddress((void**)&p_sh,   g_bnsh);

    // 1. batchnorm1
    bn_kernel<<<512, 256>>>(x, n1_g, n1_b, p_xn);
    // 2. q grouped conv
    gconv_kernel<<<dim3(16, 16), 256>>>(p_xn, q_w, p_q, Pp);
    // 3. fused dwconv+gelu -> offsets -> grid
    dwoff_kernel<<<16, 512>>>(p_q, off_dw_w, off_dw_b, off_pw_w, p_grid);
    // 4. CPB bias MLP (B-persistent HMMA)  <-- ncu capture slot
    {
        int smem = 2*128*BPAD*2 + (256 + 128 + 128 + 128 + 4*72) * 4;
        cudaFuncSetAttribute(bias_mma_kernel, cudaFuncAttributeMaxDynamicSharedMemorySize, smem);
        bias_mma_kernel<<<dim3(64, 16), 128, smem>>>(p_grid, cpb_w0, cpb_b0, cpb_w1, cpb_b1,
                                                     cpb_w2, cpb_b2, p_bias);
    }
    // 5. k + v grouped convs with inline bilinear sampling
    gconv_kv_kernel<<<16, 256>>>(p_xn, p_grid, k_w, v_w, p_k, p_v);
    // 6. fused attention
    {
        int smem = (128*65 + 64*64 + 64*64) * 4;
        cudaFuncSetAttribute(attn_fused_kernel, cudaFuncAttributeMaxDynamicSharedMemorySize, smem);
        attn_fused_kernel<<<dim3(8, 16), 128, smem>>>(p_q, p_k, p_v, p_bias, p_ao);
    }
    // 7. out projection + residual (PT=64 -> 128 blocks)
    gemm_tf32_kernel<64><<<dim3(16, 4, 2), 256>>>(p_ao, out_w, out_b, x, p_x1, 512, 0, nullptr, nullptr);
    // 8. batchnorm2 stats
    bn_stats_kernel<<<512, 256>>>(p_x1, n2_g, n2_b, p_sc, p_sh);
    // 9. mlp1 + gelu (bn2 affine fused, PT=128)
    gemm_tf32_kernel<128><<<dim3(8, 16, 2), 256>>>(p_x1, mlp_w1, mlp_b1, nullptr, p_m1, 512, 1, p_sc, p_sh);
    // 10. mlp2 + residual (PT=64 -> 128 blocks)
    gemm_tf32_kernel<64><<<dim3(16, 4, 2), 256>>>(p_m1, mlp_w2, mlp_b2, p_x1, out, 2048, 0, nullptr, nullptr);
}

// round 13
// speedup vs baseline: 1.6461x; 1.0591x over previous
#include <cuda_runtime.h>
#include <cuda_bf16.h>
#include <stdint.h>
#include <math.h>

// Problem constants
#define Bsz 2
#define Cch 512
#define Gg  8
#define Cg  64
#define Pp  1024          // H*W
#define P2  64            // H2*W2
#define SCALE 0.125f

// ---------------- scratch ----------------
__device__ float g_xn  [Bsz*Cch*Pp];
__device__ float g_q   [Bsz*Cch*Pp];
__device__ float g_grid[16*P2*2];
__device__ float g_k   [Bsz*Cch*P2];
__device__ float g_v   [Bsz*Cch*P2];
__device__ float g_bias[16*P2*Pp];       // [bg][j][i]
__device__ float g_ao  [Bsz*Cch*Pp];
__device__ float g_x1  [Bsz*Cch*Pp];
__device__ float g_m1  [Bsz*2048*Pp];
__device__ float g_bnsc[Cch];
__device__ float g_bnsh[Cch];

// ---------------- batchnorm (full) ----------------
__global__ void bn_kernel(const float* __restrict__ x, const float* __restrict__ g,
                          const float* __restrict__ b, float* __restrict__ y) {
    int c = blockIdx.x, t = threadIdx.x;
    __shared__ float ssum[256], ssq[256];
    float s = 0.f, q = 0.f;
    for (int idx = t; idx < 2048; idx += 256) {
        int bb = idx >> 10, p = idx & 1023;
        float v = x[bb*(Cch*Pp) + c*Pp + p];
        s += v; q += v*v;
    }
    ssum[t] = s; ssq[t] = q; __syncthreads();
    for (int o = 128; o > 0; o >>= 1) {
        if (t < o) { ssum[t] += ssum[t+o]; ssq[t] += ssq[t+o]; }
        __syncthreads();
    }
    float m  = ssum[0] * (1.f/2048.f);
    float var = ssq[0] * (1.f/2048.f) - m*m;
    float rs = rsqrtf(var + 1e-5f);
    float gg = g[c] * rs;
    float bb2 = b[c] - m * gg;
    for (int idx = t; idx < 2048; idx += 256) {
        int bb = idx >> 10, p = idx & 1023;
        y[bb*(Cch*Pp) + c*Pp + p] = x[bb*(Cch*Pp) + c*Pp + p] * gg + bb2;
    }
}

// ---------------- batchnorm stats only ----------------
__global__ void bn_stats_kernel(const float* __restrict__ x, const float* __restrict__ g,
                                const float* __restrict__ b, float* __restrict__ sc,
                                float* __restrict__ sh) {
    int c = blockIdx.x, t = threadIdx.x;
    __shared__ float ssum[256], ssq[256];
    float s = 0.f, q = 0.f;
    for (int idx = t; idx < 2048; idx += 256) {
        int bb = idx >> 10, p = idx & 1023;
        float v = x[bb*(Cch*Pp) + c*Pp + p];
        s += v; q += v*v;
    }
    ssum[t] = s; ssq[t] = q; __syncthreads();
    for (int o = 128; o > 0; o >>= 1) {
        if (t < o) { ssum[t] += ssum[t+o]; ssq[t] += ssq[t+o]; }
        __syncthreads();
    }
    if (t == 0) {
        float m  = ssum[0] * (1.f/2048.f);
        float var = ssq[0] * (1.f/2048.f) - m*m;
        float rs = rsqrtf(var + 1e-5f);
        float gg = g[c] * rs;
        sc[c] = gg;
        sh[c] = b[c] - m * gg;
    }
}

// ---------------- grouped 1x1 conv (q) ----------------
__global__ void gconv_kernel(const float* __restrict__ in, const float* __restrict__ w,
                             float* __restrict__ out, int P) {
    int bg = blockIdx.x, pt = blockIdx.y;
    int grp = bg & 7;
    const float* A  = in + (size_t)bg*Cg*P + pt*64;
    const float* Wg = w + grp*4096;
    float* O        = out + (size_t)bg*Cg*P + pt*64;
    __shared__ float As[64][64];
    __shared__ float Ws[64][64];
    int t = threadIdx.x;
    for (int idx = t; idx < 4096; idx += 256) {
        int r = idx >> 6, q = idx & 63;
        As[r][q] = A[r*P + q];
        ((float*)Ws)[idx] = Wg[idx];
    }
    __syncthreads();
    int tp = (t & 15) * 4, to = (t >> 4) * 4;
    float acc[4][4] = {};
    #pragma unroll
    for (int c = 0; c < 64; c += 4) {
        float4 a[4], wv[4];
        #pragma unroll
        for (int u = 0; u < 4; u++) a[u] = *(const float4*)&As[c+u][tp];
        #pragma unroll
        for (int oi = 0; oi < 4; oi++) wv[oi] = *(const float4*)&Ws[to+oi][c];
        #pragma unroll
        for (int oi = 0; oi < 4; oi++) {
            float wf[4] = {wv[oi].x, wv[oi].y, wv[oi].z, wv[oi].w};
            #pragma unroll
            for (int u = 0; u < 4; u++) {
                acc[oi][0] += wf[u]*a[u].x; acc[oi][1] += wf[u]*a[u].y;
                acc[oi][2] += wf[u]*a[u].z; acc[oi][3] += wf[u]*a[u].w;
            }
        }
    }
    #pragma unroll
    for (int oi = 0; oi < 4; oi++)
        #pragma unroll
        for (int pj = 0; pj < 4; pj++)
            O[(to+oi)*P + tp+pj] = acc[oi][pj];
}

// ---------------- fused depthwise conv+gelu -> pointwise offsets -> grid ----------------
__global__ void dwoff_kernel(const float* __restrict__ q, const float* __restrict__ dw,
                             const float* __restrict__ db, const float* __restrict__ pw,
                             float* __restrict__ grid) {
    __shared__ float off1s[Cg*P2];
    __shared__ float part[2][8][64];
    int bg = blockIdx.x, t = threadIdx.x;

    for (int idx = t; idx < Cg*P2; idx += 512) {
        int p = idx & 63, c = idx >> 6;
        int oy = p >> 3, ox = p & 7;
        float acc = db[c];
        const float* ip = q + (size_t)bg*Cg*Pp + c*Pp;
        const float* wp = dw + c*36;
        #pragma unroll
        for (int ky = 0; ky < 6; ky++) {
            int iy = oy*4 - 1 + ky;
            if (iy < 0 || iy >= 32) continue;
            #pragma unroll
            for (int kx = 0; kx < 6; kx++) {
                int ix = ox*4 - 1 + kx;
                if (ix < 0 || ix >= 32) continue;
                acc += ip[iy*32 + ix] * wp[ky*6 + kx];
            }
        }
        off1s[idx] = 0.5f * acc * (1.f + erff(acc * 0.70710678118654752f));
    }
    __syncthreads();

    int qd = t >> 6, p = t & 63;
    float s0 = 0.f, s1 = 0.f;
    #pragma unroll
    for (int cc = 0; cc < 8; cc++) {
        int c = qd*8 + cc;
        float v = off1s[c*64 + p];
        s0 = fmaf(v, pw[c], s0);
        s1 = fmaf(v, pw[64 + c], s1);
    }
    part[0][qd][p] = s0;
    part[1][qd][p] = s1;
    __syncthreads();
    if (t < 64) {
        float t0 = 0.f, t1 = 0.f;
        #pragma unroll
        for (int u = 0; u < 8; u++) { t0 += part[0][u][t]; t1 += part[1][u][t]; }
        float ox = tanhf(t0) * 4.f, oy = tanhf(t1) * 4.f;
        float gx = (float)(t & 7), gy = (float)(t >> 3);
        grid[bg*128 + t*2]   = 2.f * (gx + ox) * (1.f/7.f) - 1.f;
        grid[bg*128 + t*2+1] = 2.f * (gy + oy) * (1.f/7.f) - 1.f;
    }
}

// ======================= CPB bias MLP — HMMA, B-persistent, aliased smem =======================
#define BPAD 136   // bf16 row stride (halfs); 272B = 16B-aligned

__device__ __forceinline__ void ldsm4(uint32_t addr, uint32_t& r0, uint32_t& r1,
                                      uint32_t& r2, uint32_t& r3) {
    asm volatile("ldmatrix.sync.aligned.m8n8.x4.shared.b16 {%0,%1,%2,%3}, [%4];"
                 : "=r"(r0), "=r"(r1), "=r"(r2), "=r"(r3) : "r"(addr));
}
__device__ __forceinline__ void mma_bf16(float* c, const uint32_t* a, uint32_t b0, uint32_t b1) {
    asm volatile("mma.sync.aligned.m16n8k16.row.col.f32.bf16.bf16.f32 "
                 "{%0,%1,%2,%3}, {%4,%5,%6,%7}, {%8,%9}, {%0,%1,%2,%3};"
                 : "+f"(c[0]), "+f"(c[1]), "+f"(c[2]), "+f"(c[3])
                 : "r"(a[0]), "r"(a[1]), "r"(a[2]), "r"(a[3]), "r"(b0), "r"(b1));
}

// block: 128 thr (4 warps), one j. warp owns n-quarter [warp*32, warp*32+32).
// B-frags persistent in regs; the W1^T staging buffer is REUSED as the H1 buffer
// after the one-time B-frag load (smem 104KB -> 38.5KB => 3 blocks/SM).
__global__ __launch_bounds__(128, 3)
void bias_mma_kernel(const float* __restrict__ grid,
                     const float* __restrict__ w0, const float* __restrict__ b0,
                     const float* __restrict__ w1, const float* __restrict__ b1,
                     const float* __restrict__ w2, const float* __restrict__ b2,
                     float* __restrict__ bias) {
    extern __shared__ unsigned char smraw[];
    __nv_bfloat16* TILE = (__nv_bfloat16*)smraw;            // 128 x BPAD: W1^T at init, H1 after
    float* w0s  = (float*)(TILE + 128*BPAD);                // 256
    float* b0s  = w0s + 256;                                // 128
    float* b1s  = b0s + 128;                                // 128
    float* w2s  = b1s + 128;                                // 128
    float* part = w2s + 128;                                // 4 x 72

    int t = threadIdx.x;
    int lane = t & 31, warp = t >> 5;
    int j = blockIdx.x, bg = blockIdx.y;

    // stage W1^T into TILE (for one-time B-frag load)
    for (int idx = t; idx < 16384; idx += 128) {
        int s = idx >> 7, n = idx & 127;
        TILE[n*BPAD + s] = __float2bfloat16(w1[idx]);
    }
    for (int idx = t; idx < 256; idx += 128) w0s[idx] = w0[idx];
    b0s[t] = b0[t];
    b1s[t] = b1[t];
    w2s[t] = w2[t];
    float kvx = grid[bg*128 + j*2], kvy = grid[bg*128 + j*2 + 1];
    float b2v = b2[0];
    __syncthreads();

    uint32_t tilebase = (uint32_t)__cvta_generic_to_shared(TILE);

    // lane mappings (identical to proven layout)
    int arow  = (lane & 7) + ((lane >> 3) & 1) * 8;
    int acolq = (lane >> 4) * 8;
    int bn_off = (lane >> 4) * 8 + (lane & 7);
    int bcol   = ((lane >> 3) & 1) * 8;
    int gid = lane >> 2, ctid = lane & 3;

    // one-time persistent B-frag load: warp's n-range = [warp*32, warp*32+32)
    uint32_t Breg[2][8][4];
    #pragma unroll
    for (int np = 0; np < 2; np++) {
        int n = warp*32 + np*16 + bn_off;
        #pragma unroll
        for (int k8 = 0; k8 < 8; k8++) {
            uint32_t addr = tilebase + (uint32_t)(n*BPAD + k8*16 + bcol) * 2u;
            ldsm4(addr, Breg[np][k8][0], Breg[np][k8][1], Breg[np][k8][2], Breg[np][k8][3]);
        }
    }
    // b1/w2 values for this warp's columns (per nt): n = warp*32 + nt*8 + 2*ctid
    float b1r[4][2], w2r[4][2];
    #pragma unroll
    for (int nt = 0; nt < 4; nt++) {
        int n = warp*32 + nt*8 + 2*ctid;
        b1r[nt][0] = b1s[n];   b1r[nt][1] = b1s[n+1];
        w2r[nt][0] = w2s[n];   w2r[nt][1] = w2s[n+1];
    }
    __syncthreads();   // all B-frags in regs; TILE is now free -> becomes H1

    float* brow = bias + (size_t)bg*(P2*Pp) + (size_t)j*Pp;

    for (int it = 0; it < 8; it++) {
        int i0 = it*128;
        // build H1 row t (16 x STS.128) into TILE
        {
            int i = i0 + t;
            float qx = 2.f * (float)(i & 31) * (1.f/31.f) - 1.f;
            float qy = 2.f * (float)(i >> 5) * (1.f/31.f) - 1.f;
            float px = qx - kvx, py = qy - kvy;
            float fx = copysignf(log1pf(fabsf(px)), px);
            float fy = copysignf(log1pf(fabsf(py)), py);
            uint32_t rowb = (uint32_t)(t*BPAD) * 2u;
            #pragma unroll
            for (int c8 = 0; c8 < 16; c8++) {
                uint32_t u[4];
                #pragma unroll
                for (int e = 0; e < 4; e++) {
                    int s = c8*8 + e*2;
                    float h0 = fmaxf(fmaf(fy, w0s[128+s],   fmaf(fx, w0s[s],   b0s[s])),   0.f);
                    float h1 = fmaxf(fmaf(fy, w0s[128+s+1], fmaf(fx, w0s[s+1], b0s[s+1])), 0.f);
                    __nv_bfloat162 pr = __floats2bfloat162_rn(h0, h1);
                    u[e] = *(uint32_t*)&pr;
                }
                *(uint4*)((char*)TILE + rowb + c8*16) = make_uint4(u[0], u[1], u[2], u[3]);
            }
        }
        __syncthreads();

        #pragma unroll
        for (int sub = 0; sub < 2; sub++) {
            int r0 = sub*64;
            float c[4][4][4];
            #pragma unroll
            for (int mt = 0; mt < 4; mt++)
                #pragma unroll
                for (int nt = 0; nt < 4; nt++)
                    #pragma unroll
                    for (int f = 0; f < 4; f++) c[mt][nt][f] = 0.f;

            #pragma unroll
            for (int k8 = 0; k8 < 8; k8++) {
                uint32_t A[4][4];
                #pragma unroll
                for (int mt = 0; mt < 4; mt++) {
                    int row = r0 + mt*16 + arow;
                    uint32_t addr = tilebase + (uint32_t)(row*BPAD + k8*16 + acolq) * 2u;
                    ldsm4(addr, A[mt][0], A[mt][1], A[mt][2], A[mt][3]);
                }
                #pragma unroll
                for (int nt = 0; nt < 4; nt++) {
                    uint32_t bb0 = Breg[nt>>1][k8][(nt&1)*2];
                    uint32_t bb1 = Breg[nt>>1][k8][(nt&1)*2+1];
                    #pragma unroll
                    for (int mt = 0; mt < 4; mt++)
                        mma_bf16(c[mt][nt], A[mt], bb0, bb1);
                }
            }

            // epilogue: per-lane partial over warp's 32 n's
            #pragma unroll
            for (int mt = 0; mt < 4; mt++) {
                float v0 = 0.f, v1 = 0.f;
                #pragma unroll
                for (int nt = 0; nt < 4; nt++) {
                    v0 += fmaxf(c[mt][nt][0]+b1r[nt][0], 0.f)*w2r[nt][0]
                        + fmaxf(c[mt][nt][1]+b1r[nt][1], 0.f)*w2r[nt][1];
                    v1 += fmaxf(c[mt][nt][2]+b1r[nt][0], 0.f)*w2r[nt][0]
                        + fmaxf(c[mt][nt][3]+b1r[nt][1], 0.f)*w2r[nt][1];
                }
                v0 += __shfl_xor_sync(0xffffffffu, v0, 1);
                v0 += __shfl_xor_sync(0xffffffffu, v0, 2);
                v1 += __shfl_xor_sync(0xffffffffu, v1, 1);
                v1 += __shfl_xor_sync(0xffffffffu, v1, 2);
                if (ctid == 0) {
                    part[warp*72 + mt*16 + gid]     = v0;
                    part[warp*72 + mt*16 + gid + 8] = v1;
                }
            }
            __syncthreads();
            if (t < 64) {
                float sum = part[t] + part[72 + t] + part[144 + t] + part[216 + t];
                brow[i0 + r0 + t] = sum + b2v;
            }
            __syncthreads();
        }
    }
}

// ---------------- gconv k,v with inline bilinear sampling ----------------
__global__ void gconv_kv_kernel(const float* __restrict__ xn, const float* __restrict__ grid,
                                const float* __restrict__ kw, const float* __restrict__ vw,
                                float* __restrict__ kout, float* __restrict__ vout) {
    const int P = P2;
    int bg = blockIdx.x;
    int grp = bg & 7;
    __shared__ float sgrid[128];
    __shared__ float As[64][64];
    __shared__ float Wk[64][64];
    __shared__ float Wv[64][64];
    int t = threadIdx.x;
    if (t < 128) sgrid[t] = grid[bg*128 + t];
    for (int idx = t; idx < 4096; idx += 256) {
        ((float*)Wk)[idx] = kw[grp*4096 + idx];
        ((float*)Wv)[idx] = vw[grp*4096 + idx];
    }
    __syncthreads();
    for (int idx = t; idx < 4096; idx += 256) {
        int p = idx & 63, c = idx >> 6;
        float vx = sgrid[p*2], vy = sgrid[p*2+1];
        float x = ((vx + 1.f) * 32.f - 1.f) * 0.5f;
        float y = ((vy + 1.f) * 32.f - 1.f) * 0.5f;
        float x0f = floorf(x), y0f = floorf(y);
        int x0 = (int)x0f, y0 = (int)y0f;
        float wx = x - x0f, wy = y - y0f;
        const float* im = xn + (size_t)bg*Cg*Pp + c*Pp;
        float v00 = (x0   >= 0 && x0   < 32 && y0   >= 0 && y0   < 32) ? im[y0*32 + x0]       : 0.f;
        float v10 = (x0+1 >= 0 && x0+1 < 32 && y0   >= 0 && y0   < 32) ? im[y0*32 + x0+1]     : 0.f;
        float v01 = (x0   >= 0 && x0   < 32 && y0+1 >= 0 && y0+1 < 32) ? im[(y0+1)*32 + x0]   : 0.f;
        float v11 = (x0+1 >= 0 && x0+1 < 32 && y0+1 >= 0 && y0+1 < 32) ? im[(y0+1)*32 + x0+1] : 0.f;
        As[c][p] = v00*(1.f-wx)*(1.f-wy) + v10*wx*(1.f-wy) + v01*(1.f-wx)*wy + v11*wx*wy;
    }
    __syncthreads();
    int tp = (t & 15) * 4, to = (t >> 4) * 4;
    float ak[4][4] = {}, av[4][4] = {};
    #pragma unroll
    for (int c = 0; c < 64; c += 4) {
        float4 a[4], wk[4], wv[4];
        #pragma unroll
        for (int u = 0; u < 4; u++) a[u] = *(const float4*)&As[c+u][tp];
        #pragma unroll
        for (int oi = 0; oi < 4; oi++) {
            wk[oi] = *(const float4*)&Wk[to+oi][c];
            wv[oi] = *(const float4*)&Wv[to+oi][c];
        }
        #pragma unroll
        for (int oi = 0; oi < 4; oi++) {
            float kf[4] = {wk[oi].x, wk[oi].y, wk[oi].z, wk[oi].w};
            float vf[4] = {wv[oi].x, wv[oi].y, wv[oi].z, wv[oi].w};
            #pragma unroll
            for (int u = 0; u < 4; u++) {
                ak[oi][0] += kf[u]*a[u].x; ak[oi][1] += kf[u]*a[u].y;
                ak[oi][2] += kf[u]*a[u].z; ak[oi][3] += kf[u]*a[u].w;
                av[oi][0] += vf[u]*a[u].x; av[oi][1] += vf[u]*a[u].y;
                av[oi][2] += vf[u]*a[u].z; av[oi][3] += vf[u]*a[u].w;
            }
        }
    }
    float* KO = kout + (size_t)bg*Cg*P;
    float* VO = vout + (size_t)bg*Cg*P;
    #pragma unroll
    for (int oi = 0; oi < 4; oi++)
        #pragma unroll
        for (int pj = 0; pj < 4; pj++) {
            KO[(to+oi)*P + tp+pj] = ak[oi][pj];
            VO[(to+oi)*P + tp+pj] = av[oi][pj];
        }
}

// ======================= fused attention (transposed bias read) =======================
__global__ __launch_bounds__(128, 1)
void attn_fused_kernel(const float* __restrict__ q, const float* __restrict__ k,
                       const float* __restrict__ v, const float* __restrict__ bias,
                       float* __restrict__ out) {
    extern __shared__ float sm[];
    float* att = sm;               // [128][65]
    float* ks  = att + 128*65;     // [64][64]
    float* vs  = ks + 64*64;       // [64][64]

    int t = threadIdx.x;
    int i0 = blockIdx.x * 128, bh = blockIdx.y;
    int b = bh >> 3, h = bh & 7;

    const float* kb = k + ((size_t)b*Cch + h*64)*P2;
    const float* vb = v + ((size_t)b*Cch + h*64)*P2;
    const float* qb = q + ((size_t)b*Cch + h*64)*Pp;
    const float* bb = bias + (size_t)bh*(P2*Pp);    // [j][i]
    float* ob = out + ((size_t)b*Cch + h*64)*Pp;

    for (int idx = t; idx < 4096; idx += 128) {
        ks[idx] = kb[idx];
        vs[idx] = vb[idx];
    }
    for (int idx = t; idx < 128*64; idx += 128) {
        int jj = idx >> 7, i = idx & 127;
        att[i*65 + jj] = bb[(size_t)jj*Pp + i0 + i];
    }
    float ql[64];
    #pragma unroll
    for (int d = 0; d < 64; d++) ql[d] = qb[d*Pp + i0 + t] * SCALE;
    __syncthreads();

    float* arow = att + t*65;
    float mx = -1e30f;
    #pragma unroll 2
    for (int jj = 0; jj < 64; jj++) {
        float s = arow[jj];
        #pragma unroll
        for (int d = 0; d < 64; d++) s += ql[d] * ks[d*64 + jj];
        arow[jj] = s;
        mx = fmaxf(mx, s);
    }
    float sum = 0.f;
    #pragma unroll 4
    for (int jj = 0; jj < 64; jj++) {
        float e = __expf(arow[jj] - mx);
        arow[jj] = e;
        sum += e;
    }
    float inv = 1.f / sum;

    int i = i0 + t;
    #pragma unroll
    for (int half = 0; half < 2; half++) {
        float o[32];
        #pragma unroll
        for (int d = 0; d < 32; d++) o[d] = 0.f;
        #pragma unroll 2
        for (int jj = 0; jj < 64; jj++) {
            float a = arow[jj];
            #pragma unroll
            for (int d = 0; d < 32; d++) o[d] += a * vs[(half*32 + d)*64 + jj];
        }
        #pragma unroll
        for (int d = 0; d < 32; d++) ob[(size_t)(half*32 + d)*Pp + i] = o[d] * inv;
    }
}

// ======================= tf32 GEMM — templated p-tile =======================
__device__ __forceinline__ uint32_t f2tf32(float v) {
    uint32_t u;
    asm("cvt.rna.tf32.f32 %0, %1;" : "=r"(u) : "f"(v));
    return u;
}
__device__ __forceinline__ void mma_tf32(float* c, const uint32_t* a, uint32_t b0, uint32_t b1) {
    asm volatile("mma.sync.aligned.m16n8k8.row.col.f32.tf32.tf32.f32 "
                 "{%0,%1,%2,%3}, {%4,%5,%6,%7}, {%8,%9}, {%0,%1,%2,%3};"
                 : "+f"(c[0]), "+f"(c[1]), "+f"(c[2]), "+f"(c[3])
                 : "r"(a[0]), "r"(a[1]), "r"(a[2]), "r"(a[3]), "r"(b0), "r"(b1));
}

// PT = p-tile width (64 or 128). block 256 thr, o-tile 128.
template<int PT>
__global__ __launch_bounds__(256)
void gemm_tf32_kernel(const float* __restrict__ A, const float* __restrict__ W,
                      const float* __restrict__ bias, const float* __restrict__ res,
                      float* __restrict__ out, int Cin, int act,
                      const float* __restrict__ bnsc, const float* __restrict__ bnsh) {
    const int P = 1024;
    const int NT = PT / 16;            // n-tiles per warp
    int b = blockIdx.z;
    int O = gridDim.y * 128;
    int p0 = blockIdx.x * PT, o0 = blockIdx.y * 128;
    const float* Ab = A + (size_t)b*Cin*P;

    __shared__ float Wt[128][36];      // [o][c]
    __shared__ float Xt[32][PT + 8];   // [c][p]

    int t = threadIdx.x;
    int lane = t & 31, warp = t >> 5;
    int gid = lane >> 2, ctid = lane & 3;
    int m0w = (warp >> 1) * 32, n0w = (warp & 1) * (PT/2);

    float c[2][NT][4];
    #pragma unroll
    for (int mt = 0; mt < 2; mt++)
        #pragma unroll
        for (int nt = 0; nt < NT; nt++)
            #pragma unroll
            for (int f = 0; f < 4; f++) c[mt][nt][f] = 0.f;

    for (int cc = 0; cc < Cin; cc += 32) {
        __syncthreads();
        #pragma unroll
        for (int idx = t; idx < 1024; idx += 256) {
            int r = idx >> 3, q4 = (idx & 7) * 4;
            float4 wv = *(const float4*)&W[(size_t)(o0 + r)*Cin + cc + q4];
            *(float4*)&Wt[r][q4] = wv;
        }
        #pragma unroll
        for (int idx = t; idx < 32*(PT/4); idx += 256) {
            int r = idx / (PT/4), q4 = (idx % (PT/4)) * 4;
            float4 xv = *(const float4*)&Ab[(size_t)(cc + r)*P + p0 + q4];
            if (bnsc) {
                float s = bnsc[cc + r], h = bnsh[cc + r];
                xv.x = fmaf(xv.x, s, h); xv.y = fmaf(xv.y, s, h);
                xv.z = fmaf(xv.z, s, h); xv.w = fmaf(xv.w, s, h);
            }
            *(float4*)&Xt[r][q4] = xv;
        }
        __syncthreads();
        #pragma unroll
        for (int k0 = 0; k0 < 32; k0 += 8) {
            uint32_t a[2][4];
            #pragma unroll
            for (int mt = 0; mt < 2; mt++) {
                int row = m0w + mt*16;
                a[mt][0] = f2tf32(Wt[row + gid    ][k0 + ctid]);
                a[mt][1] = f2tf32(Wt[row + 8 + gid][k0 + ctid]);
                a[mt][2] = f2tf32(Wt[row + gid    ][k0 + ctid + 4]);
                a[mt][3] = f2tf32(Wt[row + 8 + gid][k0 + ctid + 4]);
            }
            #pragma unroll
            for (int nt = 0; nt < NT; nt++) {
                int n = n0w + nt*8 + gid;
                uint32_t b0v = f2tf32(Xt[k0 + ctid    ][n]);
                uint32_t b1v = f2tf32(Xt[k0 + ctid + 4][n]);
                mma_tf32(c[0][nt], a[0], b0v, b1v);
                mma_tf32(c[1][nt], a[1], b0v, b1v);
            }
        }
    }

    float* ob = out + (size_t)b*O*P;
    const float* rb = res ? res + (size_t)b*O*P : nullptr;
    #pragma unroll
    for (int mt = 0; mt < 2; mt++) {
        #pragma unroll
        for (int half = 0; half < 2; half++) {
            int o = o0 + m0w + mt*16 + gid + half*8;
            float bv = bias[o];
            #pragma unroll
            for (int nt = 0; nt < NT; nt++) {
                int p = p0 + n0w + nt*8 + 2*ctid;
                float v0 = c[mt][nt][half*2+0] + bv;
                float v1 = c[mt][nt][half*2+1] + bv;
                if (act == 1) {
                    v0 = 0.5f * v0 * (1.f + erff(v0 * 0.70710678118654752f));
                    v1 = 0.5f * v1 * (1.f + erff(v1 * 0.70710678118654752f));
                }
                if (rb) {
                    const float2 rv = *(const float2*)&rb[(size_t)o*P + p];
                    v0 += rv.x; v1 += rv.y;
                }
                float2 st; st.x = v0; st.y = v1;
                *(float2*)&ob[(size_t)o*P + p] = st;
            }
        }
    }
}

// ---------------- launch ----------------
extern "C" void kernel_launch(void* const* d_in, const int* in_sizes, int n_in,
                              void* d_out, int out_size) {
    const float* x        = (const float*)d_in[0];
    const float* n1_g     = (const float*)d_in[1];
    const float* n1_b     = (const float*)d_in[2];
    const float* n2_g     = (const float*)d_in[3];
    const float* n2_b     = (const float*)d_in[4];
    const float* q_w      = (const float*)d_in[5];
    const float* k_w      = (const float*)d_in[6];
    const float* v_w      = (const float*)d_in[7];
    const float* off_dw_w = (const float*)d_in[8];
    const float* off_dw_b = (const float*)d_in[9];
    const float* off_pw_w = (const float*)d_in[10];
    const float* cpb_w0   = (const float*)d_in[11];
    const float* cpb_b0   = (const float*)d_in[12];
    const float* cpb_w1   = (const float*)d_in[13];
    const float* cpb_b1   = (const float*)d_in[14];
    const float* cpb_w2   = (const float*)d_in[15];
    const float* cpb_b2   = (const float*)d_in[16];
    const float* out_w    = (const float*)d_in[17];
    const float* out_b    = (const float*)d_in[18];
    const float* mlp_w1   = (const float*)d_in[19];
    const float* mlp_b1   = (const float*)d_in[20];
    const float* mlp_w2   = (const float*)d_in[21];
    const float* mlp_b2   = (const float*)d_in[22];
    float* out = (float*)d_out;

    float *p_xn, *p_q, *p_grid, *p_k, *p_v, *p_bias, *p_ao, *p_x1, *p_m1, *p_sc, *p_sh;
    cudaGetSymbolAddress((void**)&p_xn,   g_xn);
    cudaGetSymbolAddress((void**)&p_q,    g_q);
    cudaGetSymbolAddress((void**)&p_grid, g_grid);
    cudaGetSymbolAddress((void**)&p_k,    g_k);
    cudaGetSymbolAddress((void**)&p_v,    g_v);
    cudaGetSymbolAddress((void**)&p_bias, g_bias);
    cudaGetSymbolAddress((void**)&p_ao,   g_ao);
    cudaGetSymbolAddress((void**)&p_x1,   g_x1);
    cudaGetSymbolAddress((void**)&p_m1,   g_m1);
    cudaGetSymbolAddress((void**)&p_sc,   g_bnsc);
    cudaGetSymbolAddress((void**)&p_sh,   g_bnsh);

    // 1. batchnorm1
    bn_kernel<<<512, 256>>>(x, n1_g, n1_b, p_xn);
    // 2. q grouped conv
    gconv_kernel<<<dim3(16, 16), 256>>>(p_xn, q_w, p_q, Pp);
    // 3. fused dwconv+gelu -> offsets -> grid
    dwoff_kernel<<<16, 512>>>(p_q, off_dw_w, off_dw_b, off_pw_w, p_grid);
    // 4. CPB bias MLP (aliased smem, 3 blocks/SM)  <-- ncu capture slot
    {
        int smem = 128*BPAD*2 + (256 + 128 + 128 + 128 + 4*72) * 4;
        cudaFuncSetAttribute(bias_mma_kernel, cudaFuncAttributeMaxDynamicSharedMemorySize, smem);
        bias_mma_kernel<<<dim3(64, 16), 128, smem>>>(p_grid, cpb_w0, cpb_b0, cpb_w1, cpb_b1,
                                                     cpb_w2, cpb_b2, p_bias);
    }
    // 5. k + v grouped convs with inline bilinear sampling
    gconv_kv_kernel<<<16, 256>>>(p_xn, p_grid, k_w, v_w, p_k, p_v);
    // 6. fused attention
    {
        int smem = (128*65 + 64*64 + 64*64) * 4;
        cudaFuncSetAttribute(attn_fused_kernel, cudaFuncAttributeMaxDynamicSharedMemorySize, smem);
        attn_fused_kernel<<<dim3(8, 16), 128, smem>>>(p_q, p_k, p_v, p_bias, p_ao);
    }
    // 7. out projection + residual (PT=64 -> 128 blocks)
    gemm_tf32_kernel<64><<<dim3(16, 4, 2), 256>>>(p_ao, out_w, out_b, x, p_x1, 512, 0, nullptr, nullptr);
    // 8. batchnorm2 stats
    bn_stats_kernel<<<512, 256>>>(p_x1, n2_g, n2_b, p_sc, p_sh);
    // 9. mlp1 + gelu (bn2 affine fused, PT=128)
    gemm_tf32_kernel<128><<<dim3(8, 16, 2), 256>>>(p_x1, mlp_w1, mlp_b1, nullptr, p_m1, 512, 1, p_sc, p_sh);
    // 10. mlp2 + residual (PT=64 -> 128 blocks)
    gemm_tf32_kernel<64><<<dim3(16, 4, 2), 256>>>(p_m1, mlp_w2, mlp_b2, p_x1, out, 2048, 0, nullptr, nullptr);
}

// round 14
// speedup vs baseline: 1.6856x; 1.0240x over previous
#include <cuda_runtime.h>
#include <cuda_bf16.h>
#include <stdint.h>
#include <math.h>

// Problem constants
#define Bsz 2
#define Cch 512
#define Gg  8
#define Cg  64
#define Pp  1024          // H*W
#define P2  64            // H2*W2
#define SCALE 0.125f

// ---------------- scratch ----------------
__device__ float g_q   [Bsz*Cch*Pp];
__device__ float g_grid[16*P2*2];
__device__ float g_k   [Bsz*Cch*P2];
__device__ float g_v   [Bsz*Cch*P2];
__device__ float g_bias[16*P2*Pp];       // [bg][j][i]
__device__ float g_ao  [Bsz*Cch*Pp];
__device__ float g_x1  [Bsz*Cch*Pp];
__device__ float g_m1  [Bsz*2048*Pp];
__device__ float g_sc1[Cch];
__device__ float g_sh1[Cch];
__device__ float g_bnsc[Cch];
__device__ float g_bnsh[Cch];

// ---------------- batchnorm stats only ----------------
__global__ void bn_stats_kernel(const float* __restrict__ x, const float* __restrict__ g,
                                const float* __restrict__ b, float* __restrict__ sc,
                                float* __restrict__ sh) {
    int c = blockIdx.x, t = threadIdx.x;
    __shared__ float ssum[256], ssq[256];
    float s = 0.f, q = 0.f;
    for (int idx = t; idx < 2048; idx += 256) {
        int bb = idx >> 10, p = idx & 1023;
        float v = x[bb*(Cch*Pp) + c*Pp + p];
        s += v; q += v*v;
    }
    ssum[t] = s; ssq[t] = q; __syncthreads();
    for (int o = 128; o > 0; o >>= 1) {
        if (t < o) { ssum[t] += ssum[t+o]; ssq[t] += ssq[t+o]; }
        __syncthreads();
    }
    if (t == 0) {
        float m  = ssum[0] * (1.f/2048.f);
        float var = ssq[0] * (1.f/2048.f) - m*m;
        float rs = rsqrtf(var + 1e-5f);
        float gg = g[c] * rs;
        sc[c] = gg;
        sh[c] = b[c] - m * gg;
    }
}

// ---------------- grouped 1x1 conv (q) with bn1 affine folded into staging ----------------
__global__ void gconv_kernel(const float* __restrict__ in, const float* __restrict__ w,
                             float* __restrict__ out, int P,
                             const float* __restrict__ sc, const float* __restrict__ sh) {
    int bg = blockIdx.x, pt = blockIdx.y;
    int grp = bg & 7;
    const float* A  = in + (size_t)bg*Cg*P + pt*64;
    const float* Wg = w + grp*4096;
    float* O        = out + (size_t)bg*Cg*P + pt*64;
    __shared__ float As[64][64];
    __shared__ float Ws[64][64];
    int t = threadIdx.x;
    for (int idx = t; idx < 4096; idx += 256) {
        int r = idx >> 6, q = idx & 63;
        int ch = grp*64 + r;
        As[r][q] = fmaf(A[r*P + q], sc[ch], sh[ch]);
        ((float*)Ws)[idx] = Wg[idx];
    }
    __syncthreads();
    int tp = (t & 15) * 4, to = (t >> 4) * 4;
    float acc[4][4] = {};
    #pragma unroll
    for (int c = 0; c < 64; c += 4) {
        float4 a[4], wv[4];
        #pragma unroll
        for (int u = 0; u < 4; u++) a[u] = *(const float4*)&As[c+u][tp];
        #pragma unroll
        for (int oi = 0; oi < 4; oi++) wv[oi] = *(const float4*)&Ws[to+oi][c];
        #pragma unroll
        for (int oi = 0; oi < 4; oi++) {
            float wf[4] = {wv[oi].x, wv[oi].y, wv[oi].z, wv[oi].w};
            #pragma unroll
            for (int u = 0; u < 4; u++) {
                acc[oi][0] += wf[u]*a[u].x; acc[oi][1] += wf[u]*a[u].y;
                acc[oi][2] += wf[u]*a[u].z; acc[oi][3] += wf[u]*a[u].w;
            }
        }
    }
    #pragma unroll
    for (int oi = 0; oi < 4; oi++)
        #pragma unroll
        for (int pj = 0; pj < 4; pj++)
            O[(to+oi)*P + tp+pj] = acc[oi][pj];
}

// ---------------- fused depthwise conv+gelu -> pointwise offsets -> grid ----------------
__global__ void dwoff_kernel(const float* __restrict__ q, const float* __restrict__ dw,
                             const float* __restrict__ db, const float* __restrict__ pw,
                             float* __restrict__ grid) {
    __shared__ float off1s[Cg*P2];
    __shared__ float part[2][8][64];
    int bg = blockIdx.x, t = threadIdx.x;

    for (int idx = t; idx < Cg*P2; idx += 512) {
        int p = idx & 63, c = idx >> 6;
        int oy = p >> 3, ox = p & 7;
        float acc = db[c];
        const float* ip = q + (size_t)bg*Cg*Pp + c*Pp;
        const float* wp = dw + c*36;
        #pragma unroll
        for (int ky = 0; ky < 6; ky++) {
            int iy = oy*4 - 1 + ky;
            if (iy < 0 || iy >= 32) continue;
            #pragma unroll
            for (int kx = 0; kx < 6; kx++) {
                int ix = ox*4 - 1 + kx;
                if (ix < 0 || ix >= 32) continue;
                acc += ip[iy*32 + ix] * wp[ky*6 + kx];
            }
        }
        off1s[idx] = 0.5f * acc * (1.f + erff(acc * 0.70710678118654752f));
    }
    __syncthreads();

    int qd = t >> 6, p = t & 63;
    float s0 = 0.f, s1 = 0.f;
    #pragma unroll
    for (int cc = 0; cc < 8; cc++) {
        int c = qd*8 + cc;
        float v = off1s[c*64 + p];
        s0 = fmaf(v, pw[c], s0);
        s1 = fmaf(v, pw[64 + c], s1);
    }
    part[0][qd][p] = s0;
    part[1][qd][p] = s1;
    __syncthreads();
    if (t < 64) {
        float t0 = 0.f, t1 = 0.f;
        #pragma unroll
        for (int u = 0; u < 8; u++) { t0 += part[0][u][t]; t1 += part[1][u][t]; }
        float ox = tanhf(t0) * 4.f, oy = tanhf(t1) * 4.f;
        float gx = (float)(t & 7), gy = (float)(t >> 3);
        grid[bg*128 + t*2]   = 2.f * (gx + ox) * (1.f/7.f) - 1.f;
        grid[bg*128 + t*2+1] = 2.f * (gy + oy) * (1.f/7.f) - 1.f;
    }
}

// ======================= CPB bias MLP — HMMA, B-persistent, 32-row subtiles =======================
#define BPAD 136   // bf16 row stride (halfs)

__device__ __forceinline__ void ldsm4(uint32_t addr, uint32_t& r0, uint32_t& r1,
                                      uint32_t& r2, uint32_t& r3) {
    asm volatile("ldmatrix.sync.aligned.m8n8.x4.shared.b16 {%0,%1,%2,%3}, [%4];"
                 : "=r"(r0), "=r"(r1), "=r"(r2), "=r"(r3) : "r"(addr));
}
__device__ __forceinline__ void mma_bf16(float* c, const uint32_t* a, uint32_t b0, uint32_t b1) {
    asm volatile("mma.sync.aligned.m16n8k16.row.col.f32.bf16.bf16.f32 "
                 "{%0,%1,%2,%3}, {%4,%5,%6,%7}, {%8,%9}, {%0,%1,%2,%3};"
                 : "+f"(c[0]), "+f"(c[1]), "+f"(c[2]), "+f"(c[3])
                 : "r"(a[0]), "r"(a[1]), "r"(a[2]), "r"(a[3]), "r"(b0), "r"(b1));
}

// block: 128 thr (4 warps), one j. warp owns n-quarter [warp*32, warp*32+32).
// B-frags persistent; TILE reused W1^T->H1; 32-row subtiles to fit 128 regs -> 4 blocks/SM.
__global__ __launch_bounds__(128, 4)
void bias_mma_kernel(const float* __restrict__ grid,
                     const float* __restrict__ w0, const float* __restrict__ b0,
                     const float* __restrict__ w1, const float* __restrict__ b1,
                     const float* __restrict__ w2, const float* __restrict__ b2,
                     float* __restrict__ bias) {
    extern __shared__ unsigned char smraw[];
    __nv_bfloat16* TILE = (__nv_bfloat16*)smraw;            // 128 x BPAD: W1^T at init, H1 after
    float* w0s  = (float*)(TILE + 128*BPAD);                // 256
    float* b0s  = w0s + 256;                                // 128
    float* b1s  = b0s + 128;                                // 128
    float* w2s  = b1s + 128;                                // 128
    float* part = w2s + 128;                                // 4 x 40

    int t = threadIdx.x;
    int lane = t & 31, warp = t >> 5;
    int j = blockIdx.x, bg = blockIdx.y;

    // stage W1^T into TILE (for one-time B-frag load)
    for (int idx = t; idx < 16384; idx += 128) {
        int s = idx >> 7, n = idx & 127;
        TILE[n*BPAD + s] = __float2bfloat16(w1[idx]);
    }
    for (int idx = t; idx < 256; idx += 128) w0s[idx] = w0[idx];
    b0s[t] = b0[t];
    b1s[t] = b1[t];
    w2s[t] = w2[t];
    float kvx = grid[bg*128 + j*2], kvy = grid[bg*128 + j*2 + 1];
    float b2v = b2[0];
    __syncthreads();

    uint32_t tilebase = (uint32_t)__cvta_generic_to_shared(TILE);

    int arow  = (lane & 7) + ((lane >> 3) & 1) * 8;
    int acolq = (lane >> 4) * 8;
    int bn_off = (lane >> 4) * 8 + (lane & 7);
    int bcol   = ((lane >> 3) & 1) * 8;
    int gid = lane >> 2, ctid = lane & 3;

    // one-time persistent B-frag load: warp's n-range = [warp*32, warp*32+32)
    uint32_t Breg[2][8][4];
    #pragma unroll
    for (int np = 0; np < 2; np++) {
        int n = warp*32 + np*16 + bn_off;
        #pragma unroll
        for (int k8 = 0; k8 < 8; k8++) {
            uint32_t addr = tilebase + (uint32_t)(n*BPAD + k8*16 + bcol) * 2u;
            ldsm4(addr, Breg[np][k8][0], Breg[np][k8][1], Breg[np][k8][2], Breg[np][k8][3]);
        }
    }
    __syncthreads();   // B-frags in regs; TILE becomes H1

    float* brow = bias + (size_t)bg*(P2*Pp) + (size_t)j*Pp;

    for (int it = 0; it < 8; it++) {
        int i0 = it*128;
        // build H1 row t (16 x STS.128) into TILE
        {
            int i = i0 + t;
            float qx = 2.f * (float)(i & 31) * (1.f/31.f) - 1.f;
            float qy = 2.f * (float)(i >> 5) * (1.f/31.f) - 1.f;
            float px = qx - kvx, py = qy - kvy;
            float fx = copysignf(log1pf(fabsf(px)), px);
            float fy = copysignf(log1pf(fabsf(py)), py);
            uint32_t rowb = (uint32_t)(t*BPAD) * 2u;
            #pragma unroll
            for (int c8 = 0; c8 < 16; c8++) {
                uint32_t u[4];
                #pragma unroll
                for (int e = 0; e < 4; e++) {
                    int s = c8*8 + e*2;
                    float h0 = fmaxf(fmaf(fy, w0s[128+s],   fmaf(fx, w0s[s],   b0s[s])),   0.f);
                    float h1 = fmaxf(fmaf(fy, w0s[128+s+1], fmaf(fx, w0s[s+1], b0s[s+1])), 0.f);
                    __nv_bfloat162 pr = __floats2bfloat162_rn(h0, h1);
                    u[e] = *(uint32_t*)&pr;
                }
                *(uint4*)((char*)TILE + rowb + c8*16) = make_uint4(u[0], u[1], u[2], u[3]);
            }
        }
        __syncthreads();

        #pragma unroll
        for (int sub = 0; sub < 4; sub++) {
            int r0 = sub*32;
            float c[2][4][4];
            #pragma unroll
            for (int mt = 0; mt < 2; mt++)
                #pragma unroll
                for (int nt = 0; nt < 4; nt++)
                    #pragma unroll
                    for (int f = 0; f < 4; f++) c[mt][nt][f] = 0.f;

            #pragma unroll
            for (int k8 = 0; k8 < 8; k8++) {
                uint32_t A[2][4];
                #pragma unroll
                for (int mt = 0; mt < 2; mt++) {
                    int row = r0 + mt*16 + arow;
                    uint32_t addr = tilebase + (uint32_t)(row*BPAD + k8*16 + acolq) * 2u;
                    ldsm4(addr, A[mt][0], A[mt][1], A[mt][2], A[mt][3]);
                }
                #pragma unroll
                for (int nt = 0; nt < 4; nt++) {
                    uint32_t bb0 = Breg[nt>>1][k8][(nt&1)*2];
                    uint32_t bb1 = Breg[nt>>1][k8][(nt&1)*2+1];
                    mma_bf16(c[0][nt], A[0], bb0, bb1);
                    mma_bf16(c[1][nt], A[1], bb0, bb1);
                }
            }

            // epilogue: b1/w2 read from smem (register relief)
            #pragma unroll
            for (int mt = 0; mt < 2; mt++) {
                float v0 = 0.f, v1 = 0.f;
                #pragma unroll
                for (int nt = 0; nt < 4; nt++) {
                    int n = warp*32 + nt*8 + 2*ctid;
                    float b1a = b1s[n], b1b = b1s[n+1];
                    float w2a = w2s[n], w2b = w2s[n+1];
                    v0 += fmaxf(c[mt][nt][0]+b1a, 0.f)*w2a + fmaxf(c[mt][nt][1]+b1b, 0.f)*w2b;
                    v1 += fmaxf(c[mt][nt][2]+b1a, 0.f)*w2a + fmaxf(c[mt][nt][3]+b1b, 0.f)*w2b;
                }
                v0 += __shfl_xor_sync(0xffffffffu, v0, 1);
                v0 += __shfl_xor_sync(0xffffffffu, v0, 2);
                v1 += __shfl_xor_sync(0xffffffffu, v1, 1);
                v1 += __shfl_xor_sync(0xffffffffu, v1, 2);
                if (ctid == 0) {
                    part[warp*40 + mt*16 + gid]     = v0;
                    part[warp*40 + mt*16 + gid + 8] = v1;
                }
            }
            __syncthreads();
            if (t < 32) {
                float sum = part[t] + part[40 + t] + part[80 + t] + part[120 + t];
                brow[i0 + r0 + t] = sum + b2v;
            }
            __syncthreads();
        }
    }
}

// ---------------- gconv k,v with inline bilinear sampling (bn1 affine folded) ----------------
__global__ void gconv_kv_kernel(const float* __restrict__ xr, const float* __restrict__ grid,
                                const float* __restrict__ kw, const float* __restrict__ vw,
                                float* __restrict__ kout, float* __restrict__ vout,
                                const float* __restrict__ sc, const float* __restrict__ sh) {
    const int P = P2;
    int bg = blockIdx.x;
    int grp = bg & 7;
    __shared__ float sgrid[128];
    __shared__ float As[64][64];
    __shared__ float Wk[64][64];
    __shared__ float Wv[64][64];
    int t = threadIdx.x;
    if (t < 128) sgrid[t] = grid[bg*128 + t];
    for (int idx = t; idx < 4096; idx += 256) {
        ((float*)Wk)[idx] = kw[grp*4096 + idx];
        ((float*)Wv)[idx] = vw[grp*4096 + idx];
    }
    __syncthreads();
    // sample raw x with (value, valid-mass) accumulation, then apply bn1 affine
    for (int idx = t; idx < 4096; idx += 256) {
        int p = idx & 63, c = idx >> 6;
        float vx = sgrid[p*2], vy = sgrid[p*2+1];
        float x = ((vx + 1.f) * 32.f - 1.f) * 0.5f;
        float y = ((vy + 1.f) * 32.f - 1.f) * 0.5f;
        float x0f = floorf(x), y0f = floorf(y);
        int x0 = (int)x0f, y0 = (int)y0f;
        float wx = x - x0f, wy = y - y0f;
        const float* im = xr + (size_t)bg*Cg*Pp + c*Pp;
        float w00 = (1.f-wx)*(1.f-wy), w10 = wx*(1.f-wy), w01 = (1.f-wx)*wy, w11 = wx*wy;
        bool p00 = (x0   >= 0 && x0   < 32 && y0   >= 0 && y0   < 32);
        bool p10 = (x0+1 >= 0 && x0+1 < 32 && y0   >= 0 && y0   < 32);
        bool p01 = (x0   >= 0 && x0   < 32 && y0+1 >= 0 && y0+1 < 32);
        bool p11 = (x0+1 >= 0 && x0+1 < 32 && y0+1 >= 0 && y0+1 < 32);
        float val = 0.f, mass = 0.f;
        if (p00) { val += w00*im[y0*32 + x0];       mass += w00; }
        if (p10) { val += w10*im[y0*32 + x0+1];     mass += w10; }
        if (p01) { val += w01*im[(y0+1)*32 + x0];   mass += w01; }
        if (p11) { val += w11*im[(y0+1)*32 + x0+1]; mass += w11; }
        int ch = grp*64 + c;
        As[c][p] = val * sc[ch] + mass * sh[ch];
    }
    __syncthreads();
    int tp = (t & 15) * 4, to = (t >> 4) * 4;
    float ak[4][4] = {}, av[4][4] = {};
    #pragma unroll
    for (int c = 0; c < 64; c += 4) {
        float4 a[4], wk[4], wv[4];
        #pragma unroll
        for (int u = 0; u < 4; u++) a[u] = *(const float4*)&As[c+u][tp];
        #pragma unroll
        for (int oi = 0; oi < 4; oi++) {
            wk[oi] = *(const float4*)&Wk[to+oi][c];
            wv[oi] = *(const float4*)&Wv[to+oi][c];
        }
        #pragma unroll
        for (int oi = 0; oi < 4; oi++) {
            float kf[4] = {wk[oi].x, wk[oi].y, wk[oi].z, wk[oi].w};
            float vf[4] = {wv[oi].x, wv[oi].y, wv[oi].z, wv[oi].w};
            #pragma unroll
            for (int u = 0; u < 4; u++) {
                ak[oi][0] += kf[u]*a[u].x; ak[oi][1] += kf[u]*a[u].y;
                ak[oi][2] += kf[u]*a[u].z; ak[oi][3] += kf[u]*a[u].w;
                av[oi][0] += vf[u]*a[u].x; av[oi][1] += vf[u]*a[u].y;
                av[oi][2] += vf[u]*a[u].z; av[oi][3] += vf[u]*a[u].w;
            }
        }
    }
    float* KO = kout + (size_t)bg*Cg*P;
    float* VO = vout + (size_t)bg*Cg*P;
    #pragma unroll
    for (int oi = 0; oi < 4; oi++)
        #pragma unroll
        for (int pj = 0; pj < 4; pj++) {
            KO[(to+oi)*P + tp+pj] = ak[oi][pj];
            VO[(to+oi)*P + tp+pj] = av[oi][pj];
        }
}

// ======================= fused attention (transposed bias read) =======================
__global__ __launch_bounds__(128, 1)
void attn_fused_kernel(const float* __restrict__ q, const float* __restrict__ k,
                       const float* __restrict__ v, const float* __restrict__ bias,
                       float* __restrict__ out) {
    extern __shared__ float sm[];
    float* att = sm;               // [128][65]
    float* ks  = att + 128*65;     // [64][64]
    float* vs  = ks + 64*64;       // [64][64]

    int t = threadIdx.x;
    int i0 = blockIdx.x * 128, bh = blockIdx.y;
    int b = bh >> 3, h = bh & 7;

    const float* kb = k + ((size_t)b*Cch + h*64)*P2;
    const float* vb = v + ((size_t)b*Cch + h*64)*P2;
    const float* qb = q + ((size_t)b*Cch + h*64)*Pp;
    const float* bb = bias + (size_t)bh*(P2*Pp);    // [j][i]
    float* ob = out + ((size_t)b*Cch + h*64)*Pp;

    for (int idx = t; idx < 4096; idx += 128) {
        ks[idx] = kb[idx];
        vs[idx] = vb[idx];
    }
    for (int idx = t; idx < 128*64; idx += 128) {
        int jj = idx >> 7, i = idx & 127;
        att[i*65 + jj] = bb[(size_t)jj*Pp + i0 + i];
    }
    float ql[64];
    #pragma unroll
    for (int d = 0; d < 64; d++) ql[d] = qb[d*Pp + i0 + t] * SCALE;
    __syncthreads();

    float* arow = att + t*65;
    float mx = -1e30f;
    #pragma unroll 2
    for (int jj = 0; jj < 64; jj++) {
        float s = arow[jj];
        #pragma unroll
        for (int d = 0; d < 64; d++) s += ql[d] * ks[d*64 + jj];
        arow[jj] = s;
        mx = fmaxf(mx, s);
    }
    float sum = 0.f;
    #pragma unroll 4
    for (int jj = 0; jj < 64; jj++) {
        float e = __expf(arow[jj] - mx);
        arow[jj] = e;
        sum += e;
    }
    float inv = 1.f / sum;

    int i = i0 + t;
    #pragma unroll
    for (int half = 0; half < 2; half++) {
        float o[32];
        #pragma unroll
        for (int d = 0; d < 32; d++) o[d] = 0.f;
        #pragma unroll 2
        for (int jj = 0; jj < 64; jj++) {
            float a = arow[jj];
            #pragma unroll
            for (int d = 0; d < 32; d++) o[d] += a * vs[(half*32 + d)*64 + jj];
        }
        #pragma unroll
        for (int d = 0; d < 32; d++) ob[(size_t)(half*32 + d)*Pp + i] = o[d] * inv;
    }
}

// ======================= tf32 GEMM — templated p-tile =======================
__device__ __forceinline__ uint32_t f2tf32(float v) {
    uint32_t u;
    asm("cvt.rna.tf32.f32 %0, %1;" : "=r"(u) : "f"(v));
    return u;
}
__device__ __forceinline__ void mma_tf32(float* c, const uint32_t* a, uint32_t b0, uint32_t b1) {
    asm volatile("mma.sync.aligned.m16n8k8.row.col.f32.tf32.tf32.f32 "
                 "{%0,%1,%2,%3}, {%4,%5,%6,%7}, {%8,%9}, {%0,%1,%2,%3};"
                 : "+f"(c[0]), "+f"(c[1]), "+f"(c[2]), "+f"(c[3])
                 : "r"(a[0]), "r"(a[1]), "r"(a[2]), "r"(a[3]), "r"(b0), "r"(b1));
}

// PT = p-tile width (64 or 128). block 256 thr, o-tile 128.
template<int PT>
__global__ __launch_bounds__(256)
void gemm_tf32_kernel(const float* __restrict__ A, const float* __restrict__ W,
                      const float* __restrict__ bias, const float* __restrict__ res,
                      float* __restrict__ out, int Cin, int act,
                      const float* __restrict__ bnsc, const float* __restrict__ bnsh) {
    const int P = 1024;
    const int NT = PT / 16;            // n-tiles per warp
    int b = blockIdx.z;
    int O = gridDim.y * 128;
    int p0 = blockIdx.x * PT, o0 = blockIdx.y * 128;
    const float* Ab = A + (size_t)b*Cin*P;

    __shared__ float Wt[128][36];      // [o][c]
    __shared__ float Xt[32][PT + 8];   // [c][p]

    int t = threadIdx.x;
    int lane = t & 31, warp = t >> 5;
    int gid = lane >> 2, ctid = lane & 3;
    int m0w = (warp >> 1) * 32, n0w = (warp & 1) * (PT/2);

    float c[2][NT][4];
    #pragma unroll
    for (int mt = 0; mt < 2; mt++)
        #pragma unroll
        for (int nt = 0; nt < NT; nt++)
            #pragma unroll
            for (int f = 0; f < 4; f++) c[mt][nt][f] = 0.f;

    for (int cc = 0; cc < Cin; cc += 32) {
        __syncthreads();
        #pragma unroll
        for (int idx = t; idx < 1024; idx += 256) {
            int r = idx >> 3, q4 = (idx & 7) * 4;
            float4 wv = *(const float4*)&W[(size_t)(o0 + r)*Cin + cc + q4];
            *(float4*)&Wt[r][q4] = wv;
        }
        #pragma unroll
        for (int idx = t; idx < 32*(PT/4); idx += 256) {
            int r = idx / (PT/4), q4 = (idx % (PT/4)) * 4;
            float4 xv = *(const float4*)&Ab[(size_t)(cc + r)*P + p0 + q4];
            if (bnsc) {
                float s = bnsc[cc + r], h = bnsh[cc + r];
                xv.x = fmaf(xv.x, s, h); xv.y = fmaf(xv.y, s, h);
                xv.z = fmaf(xv.z, s, h); xv.w = fmaf(xv.w, s, h);
            }
            *(float4*)&Xt[r][q4] = xv;
        }
        __syncthreads();
        #pragma unroll
        for (int k0 = 0; k0 < 32; k0 += 8) {
            uint32_t a[2][4];
            #pragma unroll
            for (int mt = 0; mt < 2; mt++) {
                int row = m0w + mt*16;
                a[mt][0] = f2tf32(Wt[row + gid    ][k0 + ctid]);
                a[mt][1] = f2tf32(Wt[row + 8 + gid][k0 + ctid]);
                a[mt][2] = f2tf32(Wt[row + gid    ][k0 + ctid + 4]);
                a[mt][3] = f2tf32(Wt[row + 8 + gid][k0 + ctid + 4]);
            }
            #pragma unroll
            for (int nt = 0; nt < NT; nt++) {
                int n = n0w + nt*8 + gid;
                uint32_t b0v = f2tf32(Xt[k0 + ctid    ][n]);
                uint32_t b1v = f2tf32(Xt[k0 + ctid + 4][n]);
                mma_tf32(c[0][nt], a[0], b0v, b1v);
                mma_tf32(c[1][nt], a[1], b0v, b1v);
            }
        }
    }

    float* ob = out + (size_t)b*O*P;
    const float* rb = res ? res + (size_t)b*O*P : nullptr;
    #pragma unroll
    for (int mt = 0; mt < 2; mt++) {
        #pragma unroll
        for (int half = 0; half < 2; half++) {
            int o = o0 + m0w + mt*16 + gid + half*8;
            float bv = bias[o];
            #pragma unroll
            for (int nt = 0; nt < NT; nt++) {
                int p = p0 + n0w + nt*8 + 2*ctid;
                float v0 = c[mt][nt][half*2+0] + bv;
                float v1 = c[mt][nt][half*2+1] + bv;
                if (act == 1) {
                    v0 = 0.5f * v0 * (1.f + erff(v0 * 0.70710678118654752f));
                    v1 = 0.5f * v1 * (1.f + erff(v1 * 0.70710678118654752f));
                }
                if (rb) {
                    const float2 rv = *(const float2*)&rb[(size_t)o*P + p];
                    v0 += rv.x; v1 += rv.y;
                }
                float2 st; st.x = v0; st.y = v1;
                *(float2*)&ob[(size_t)o*P + p] = st;
            }
        }
    }
}

// ---------------- launch ----------------
extern "C" void kernel_launch(void* const* d_in, const int* in_sizes, int n_in,
                              void* d_out, int out_size) {
    const float* x        = (const float*)d_in[0];
    const float* n1_g     = (const float*)d_in[1];
    const float* n1_b     = (const float*)d_in[2];
    const float* n2_g     = (const float*)d_in[3];
    const float* n2_b     = (const float*)d_in[4];
    const float* q_w      = (const float*)d_in[5];
    const float* k_w      = (const float*)d_in[6];
    const float* v_w      = (const float*)d_in[7];
    const float* off_dw_w = (const float*)d_in[8];
    const float* off_dw_b = (const float*)d_in[9];
    const float* off_pw_w = (const float*)d_in[10];
    const float* cpb_w0   = (const float*)d_in[11];
    const float* cpb_b0   = (const float*)d_in[12];
    const float* cpb_w1   = (const float*)d_in[13];
    const float* cpb_b1   = (const float*)d_in[14];
    const float* cpb_w2   = (const float*)d_in[15];
    const float* cpb_b2   = (const float*)d_in[16];
    const float* out_w    = (const float*)d_in[17];
    const float* out_b    = (const float*)d_in[18];
    const float* mlp_w1   = (const float*)d_in[19];
    const float* mlp_b1   = (const float*)d_in[20];
    const float* mlp_w2   = (const float*)d_in[21];
    const float* mlp_b2   = (const float*)d_in[22];
    float* out = (float*)d_out;

    float *p_q, *p_grid, *p_k, *p_v, *p_bias, *p_ao, *p_x1, *p_m1;
    float *p_sc1, *p_sh1, *p_sc, *p_sh;
    cudaGetSymbolAddress((void**)&p_q,    g_q);
    cudaGetSymbolAddress((void**)&p_grid, g_grid);
    cudaGetSymbolAddress((void**)&p_k,    g_k);
    cudaGetSymbolAddress((void**)&p_v,    g_v);
    cudaGetSymbolAddress((void**)&p_bias, g_bias);
    cudaGetSymbolAddress((void**)&p_ao,   g_ao);
    cudaGetSymbolAddress((void**)&p_x1,   g_x1);
    cudaGetSymbolAddress((void**)&p_m1,   g_m1);
    cudaGetSymbolAddress((void**)&p_sc1,  g_sc1);
    cudaGetSymbolAddress((void**)&p_sh1,  g_sh1);
    cudaGetSymbolAddress((void**)&p_sc,   g_bnsc);
    cudaGetSymbolAddress((void**)&p_sh,   g_bnsh);

    // 1. batchnorm1 stats (affine folded downstream)
    bn_stats_kernel<<<512, 256>>>(x, n1_g, n1_b, p_sc1, p_sh1);
    // 2. q grouped conv (bn1 affine in staging)
    gconv_kernel<<<dim3(16, 16), 256>>>(x, q_w, p_q, Pp, p_sc1, p_sh1);
    // 3. fused dwconv+gelu -> offsets -> grid
    dwoff_kernel<<<16, 512>>>(p_q, off_dw_w, off_dw_b, off_pw_w, p_grid);
    // 4. CPB bias MLP (4 blocks/SM target)  <-- ncu capture slot
    {
        int smem = 128*BPAD*2 + (256 + 128 + 128 + 128 + 4*40) * 4;
        cudaFuncSetAttribute(bias_mma_kernel, cudaFuncAttributeMaxDynamicSharedMemorySize, smem);
        bias_mma_kernel<<<dim3(64, 16), 128, smem>>>(p_grid, cpb_w0, cpb_b0, cpb_w1, cpb_b1,
                                                     cpb_w2, cpb_b2, p_bias);
    }
    // 5. k + v grouped convs with inline bilinear sampling (bn1 affine folded)
    gconv_kv_kernel<<<16, 256>>>(x, p_grid, k_w, v_w, p_k, p_v, p_sc1, p_sh1);
    // 6. fused attention
    {
        int smem = (128*65 + 64*64 + 64*64) * 4;
        cudaFuncSetAttribute(attn_fused_kernel, cudaFuncAttributeMaxDynamicSharedMemorySize, smem);
        attn_fused_kernel<<<dim3(8, 16), 128, smem>>>(p_q, p_k, p_v, p_bias, p_ao);
    }
    // 7. out projection + residual (PT=64 -> 128 blocks)
    gemm_tf32_kernel<64><<<dim3(16, 4, 2), 256>>>(p_ao, out_w, out_b, x, p_x1, 512, 0, nullptr, nullptr);
    // 8. batchnorm2 stats
    bn_stats_kernel<<<512, 256>>>(p_x1, n2_g, n2_b, p_sc, p_sh);
    // 9. mlp1 + gelu (bn2 affine fused, PT=128)
    gemm_tf32_kernel<128><<<dim3(8, 16, 2), 256>>>(p_x1, mlp_w1, mlp_b1, nullptr, p_m1, 512, 1, p_sc, p_sh);
    // 10. mlp2 + residual (PT=64 -> 128 blocks)
    gemm_tf32_kernel<64><<<dim3(16, 4, 2), 256>>>(p_m1, mlp_w2, mlp_b2, p_x1, out, 2048, 0, nullptr, nullptr);
}